// round 5
// baseline (speedup 1.0000x reference)
#include <cuda_runtime.h>
#include <math.h>
#include <stdint.h>

#define S_LEN 1024
#define NHEADS 128
#define DQd 192
#define DNd 128
#define DVd 128
#define DMODEL 7168
#define QLORA 1536
#define KVLORA 512
#define EQ (NHEADS * DQd)   // 24576
#define EV (NHEADS * DVd)   // 16384

// ---- scratch (__device__ globals; allocation-free rule) ----
__device__ float g_xr[(size_t)S_LEN * DMODEL];
__device__ float g_wqar[(size_t)QLORA * DMODEL];
__device__ float g_wkvar[(size_t)KVLORA * DMODEL];
__device__ float g_wqbr[(size_t)EQ * QLORA];
__device__ float g_wkbr[(size_t)EQ * KVLORA];
__device__ float g_wvbr[(size_t)EV * KVLORA];
__device__ float g_wor[(size_t)DMODEL * EV];
__device__ float g_qlp[(size_t)4 * S_LEN * QLORA];   // split-K partials
__device__ float g_kvlp[(size_t)8 * S_LEN * KVLORA];
__device__ float g_qlat[(size_t)S_LEN * QLORA];
__device__ float g_kvlat[(size_t)S_LEN * KVLORA];
__device__ float g_q[(size_t)S_LEN * EQ];
__device__ float g_k[(size_t)S_LEN * EQ];
__device__ float g_vt[(size_t)EV * S_LEN];           // V^T per head: [h*128+d][s]
__device__ float g_scores[(size_t)NHEADS * S_LEN * S_LEN];
__device__ float g_attnout[(size_t)S_LEN * EV];

__device__ __forceinline__ unsigned f2tf32(float x) {
    unsigned u;
    asm("cvt.rna.tf32.f32 %0, %1;" : "=r"(u) : "f"(x));
    return u;
}
__device__ __forceinline__ float f2tf32f(float x) { return __uint_as_float(f2tf32(x)); }

__device__ __forceinline__ void mma_tf32(float* d, const unsigned* a, const unsigned* b) {
    asm volatile(
        "mma.sync.aligned.m16n8k8.row.col.f32.tf32.tf32.f32 "
        "{%0,%1,%2,%3}, {%4,%5,%6,%7}, {%8,%9}, {%0,%1,%2,%3};"
        : "+f"(d[0]), "+f"(d[1]), "+f"(d[2]), "+f"(d[3])
        : "r"(a[0]), "r"(a[1]), "r"(a[2]), "r"(a[3]), "r"(b[0]), "r"(b[1]));
}

__device__ __forceinline__ void cp_async16(uint32_t dst, const void* src) {
    asm volatile("cp.async.cg.shared.global [%0], [%1], 16;\n" :: "r"(dst), "l"(src));
}
#define CP_COMMIT() asm volatile("cp.async.commit_group;\n" ::: "memory")
#define CP_WAIT0()  asm volatile("cp.async.wait_group 0;\n" ::: "memory")

// ---------------------------------------------------------------------------
// C[M,N] = A[M,K] @ B^T (B is [N,K] row-major). tf32 MMA, fp32 accumulate.
// Both A and B must be tf32-pre-rounded in gmem (pure cp.async staging).
// Block tile 256x128, kTile 32, 8 warps of 64x64 each. Double-buffered.
// M % 256 == 0, N % 128 == 0, K % 32 == 0.
// kChunk > 0: split-K mode; blockIdx.z selects k-window [z*kChunk, (z+1)*kChunk)
// and output plane C + z*sC. Otherwise z is a batch index via sA/sB/sC.
// Dynamic smem: (2*256 + 2*128) * 36 floats = 110592 B.
// ---------------------------------------------------------------------------
#define SROW 36
#define A_STG (256 * SROW)
#define B_STG (128 * SROW)

template <bool ROUND>
__global__ __launch_bounds__(256, 1) void gemm_nt(
    const float* __restrict__ Ag, const float* __restrict__ Bg, float* __restrict__ Cg,
    int K, int lda, int ldb, int ldc, long sA, long sB, long sC, int kChunk)
{
    extern __shared__ float sm[];
    float* SA = sm;                // [2][256][36]
    float* SB = sm + 2 * A_STG;    // [2][128][36]

    const int z = blockIdx.z;
    const float *A, *B;
    float* C;
    int Keff;
    if (kChunk) {
        A = Ag + (long)z * kChunk;
        B = Bg + (long)z * kChunk;
        C = Cg + (long)z * sC;
        Keff = kChunk;
    } else {
        A = Ag + (long)z * sA;
        B = Bg + (long)z * sB;
        C = Cg + (long)z * sC;
        Keff = K;
    }

    const int m0 = blockIdx.y * 256;
    const int n0 = blockIdx.x * 128;
    const int t = threadIdx.x, wid = t >> 5, lane = t & 31;
    const int wm = wid >> 1, wn = wid & 1;
    const int g = lane >> 2, tg = lane & 3;

    // staging: thread covers A rows {srow, srow+128} and B row srow,
    // float4 columns c4 + 2i (i = 0..3)
    const int srow = t >> 1;
    const int c4 = t & 1;
    const float* Ap0 = A + (long)(m0 + srow) * lda + c4 * 4;
    const float* Ap1 = A + (long)(m0 + srow + 128) * lda + c4 * 4;
    const float* Bp  = B + (long)(n0 + srow) * ldb + c4 * 4;
    const uint32_t sa0 = (uint32_t)__cvta_generic_to_shared(&SA[srow * SROW + c4 * 4]);
    const uint32_t sa1 = (uint32_t)__cvta_generic_to_shared(&SA[(srow + 128) * SROW + c4 * 4]);
    const uint32_t sb0 = (uint32_t)__cvta_generic_to_shared(&SB[srow * SROW + c4 * 4]);

    float acc[4][8][4] = {};

    // prologue: tile 0
#pragma unroll
    for (int i = 0; i < 4; ++i) {
        cp_async16(sa0 + i * 32, Ap0 + 8 * i);
        cp_async16(sa1 + i * 32, Ap1 + 8 * i);
        cp_async16(sb0 + i * 32, Bp + 8 * i);
    }
    CP_COMMIT();

    const int niter = Keff >> 5;
    for (int it = 0; it < niter; ++it) {
        const int cur = it & 1;
        CP_WAIT0();
        __syncthreads();

        // issue tile it+1 into the other buffer (overlaps with compute below)
        if (it + 1 < niter) {
            const int k0 = (it + 1) << 5;
            const uint32_t ao = (cur ^ 1) * (A_STG * 4);
            const uint32_t bo = (cur ^ 1) * (B_STG * 4);
#pragma unroll
            for (int i = 0; i < 4; ++i) {
                cp_async16(sa0 + ao + i * 32, Ap0 + k0 + 8 * i);
                cp_async16(sa1 + ao + i * 32, Ap1 + k0 + 8 * i);
                cp_async16(sb0 + bo + i * 32, Bp + k0 + 8 * i);
            }
            CP_COMMIT();
        }

        const float* sa = SA + cur * A_STG;
        const float* sb = SB + cur * B_STG;
#pragma unroll
        for (int kc = 0; kc < 4; ++kc) {
            const int kb = kc * 8;
            unsigned af[4][4];
#pragma unroll
            for (int mt = 0; mt < 4; ++mt) {
                const int r = wm * 64 + mt * 16 + g;
                af[mt][0] = __float_as_uint(sa[r * SROW + kb + tg]);
                af[mt][1] = __float_as_uint(sa[(r + 8) * SROW + kb + tg]);
                af[mt][2] = __float_as_uint(sa[r * SROW + kb + tg + 4]);
                af[mt][3] = __float_as_uint(sa[(r + 8) * SROW + kb + tg + 4]);
            }
#pragma unroll
            for (int nt = 0; nt < 8; ++nt) {
                const int n = wn * 64 + nt * 8 + g;
                unsigned bf[2];
                bf[0] = __float_as_uint(sb[n * SROW + kb + tg]);
                bf[1] = __float_as_uint(sb[n * SROW + kb + tg + 4]);
#pragma unroll
                for (int mt = 0; mt < 4; ++mt)
                    mma_tf32(acc[mt][nt], af[mt], bf);
            }
        }
    }

    // epilogue
#pragma unroll
    for (int mt = 0; mt < 4; ++mt) {
        const int rr = m0 + wm * 64 + mt * 16 + g;
#pragma unroll
        for (int nt = 0; nt < 8; ++nt) {
            const int cc = n0 + wn * 64 + nt * 8 + tg * 2;
            float2 v0 = make_float2(acc[mt][nt][0], acc[mt][nt][1]);
            float2 v1 = make_float2(acc[mt][nt][2], acc[mt][nt][3]);
            if (ROUND) {
                v0.x = f2tf32f(v0.x); v0.y = f2tf32f(v0.y);
                v1.x = f2tf32f(v1.x); v1.y = f2tf32f(v1.y);
            }
            *(float2*)(C + (long)rr * ldc + cc)       = v0;
            *(float2*)(C + (long)(rr + 8) * ldc + cc) = v1;
        }
    }
}

// Elementwise tf32 rounding
__global__ void round_tf32_kernel(const float* __restrict__ in, float* __restrict__ out, int n4)
{
    int i = blockIdx.x * blockDim.x + threadIdx.x;
    if (i >= n4) return;
    float4 v = ((const float4*)in)[i];
    v.x = f2tf32f(v.x); v.y = f2tf32f(v.y); v.z = f2tf32f(v.z); v.w = f2tf32f(v.w);
    ((float4*)out)[i] = v;
}

// Split-K reduce: out[i] = round(sum_p in[i + p*stride4])  (float4 granularity)
template <int P>
__global__ void reduce_k(const float* __restrict__ in, float* __restrict__ out,
                         int n4, long stride4)
{
    int i = blockIdx.x * blockDim.x + threadIdx.x;
    if (i >= n4) return;
    float4 s = ((const float4*)in)[i];
#pragma unroll
    for (int p = 1; p < P; ++p) {
        float4 v = ((const float4*)in)[i + (long)p * stride4];
        s.x += v.x; s.y += v.y; s.z += v.z; s.w += v.w;
    }
    s.x = f2tf32f(s.x); s.y = f2tf32f(s.y); s.z = f2tf32f(s.z); s.w = f2tf32f(s.w);
    ((float4*)out)[i] = s;
}

// Interleaved RoPE over dims [128,192) of each head vector. X: [S][H][192].
// Writes tf32-rounded.
__global__ void rope_kernel(float* __restrict__ X)
{
    long idx = (long)blockIdx.x * blockDim.x + threadIdx.x;
    if (idx >= (long)S_LEN * NHEADS * 32) return;
    int i = (int)(idx & 31);
    int h = (int)((idx >> 5) & (NHEADS - 1));
    int s = (int)(idx >> 12);

    int m = (2 * i) & 31;
    float invf = (float)pow(10000.0, -(double)m / 32.0);
    float ang = (float)s * invf;
    float sn, cs;
    sincosf(ang, &sn, &cs);

    float* p = X + ((long)s * NHEADS + h) * DQd + DNd + 2 * i;
    float x1 = p[0], x2 = p[1];
    p[0] = f2tf32f(x1 * cs - x2 * sn);
    p[1] = f2tf32f(x1 * sn + x2 * cs);
}

// Row softmax with 1/sqrt(192) pre-scale; writes tf32-rounded probs.
__global__ __launch_bounds__(256) void softmax_kernel(float* __restrict__ P)
{
    float* row = P + (long)blockIdx.x * S_LEN;
    const int t = threadIdx.x;
    const int lane = t & 31, wid = t >> 5;
    const float scale = 0.07216878364870323f;  // 1/sqrt(192)

    float4 v = *(float4*)(row + t * 4);
    v.x *= scale; v.y *= scale; v.z *= scale; v.w *= scale;

    __shared__ float red[8];
    float lm = fmaxf(fmaxf(v.x, v.y), fmaxf(v.z, v.w));
#pragma unroll
    for (int o = 16; o; o >>= 1) lm = fmaxf(lm, __shfl_xor_sync(0xffffffffu, lm, o));
    if (lane == 0) red[wid] = lm;
    __syncthreads();
    float mall = red[0];
#pragma unroll
    for (int i = 1; i < 8; ++i) mall = fmaxf(mall, red[i]);

    float e0 = __expf(v.x - mall);
    float e1 = __expf(v.y - mall);
    float e2 = __expf(v.z - mall);
    float e3 = __expf(v.w - mall);
    float ls = e0 + e1 + e2 + e3;
#pragma unroll
    for (int o = 16; o; o >>= 1) ls += __shfl_xor_sync(0xffffffffu, ls, o);
    __syncthreads();
    if (lane == 0) red[wid] = ls;
    __syncthreads();
    float sall = 0.f;
#pragma unroll
    for (int i = 0; i < 8; ++i) sall += red[i];
    float inv = 1.f / sall;

    float4 o4 = make_float4(f2tf32f(e0 * inv), f2tf32f(e1 * inv),
                            f2tf32f(e2 * inv), f2tf32f(e3 * inv));
    *(float4*)(row + t * 4) = o4;
}

extern "C" void kernel_launch(void* const* d_in, const int* in_sizes, int n_in,
                              void* d_out, int out_size)
{
    const float* X    = (const float*)d_in[0];
    const float* Wqa  = (const float*)d_in[1];
    const float* Wkva = (const float*)d_in[2];
    const float* Wqb  = (const float*)d_in[3];
    const float* Wkb  = (const float*)d_in[4];
    const float* Wvb  = (const float*)d_in[5];
    const float* Wo   = (const float*)d_in[6];
    float* out = (float*)d_out;

    float *xr, *wqar, *wkvar, *wqbr, *wkbr, *wvbr, *wor;
    float *qlp, *kvlp, *qlat, *kvlat, *q, *k, *vt, *sc, *ao;
    cudaGetSymbolAddress((void**)&xr, g_xr);
    cudaGetSymbolAddress((void**)&wqar, g_wqar);
    cudaGetSymbolAddress((void**)&wkvar, g_wkvar);
    cudaGetSymbolAddress((void**)&wqbr, g_wqbr);
    cudaGetSymbolAddress((void**)&wkbr, g_wkbr);
    cudaGetSymbolAddress((void**)&wvbr, g_wvbr);
    cudaGetSymbolAddress((void**)&wor, g_wor);
    cudaGetSymbolAddress((void**)&qlp, g_qlp);
    cudaGetSymbolAddress((void**)&kvlp, g_kvlp);
    cudaGetSymbolAddress((void**)&qlat, g_qlat);
    cudaGetSymbolAddress((void**)&kvlat, g_kvlat);
    cudaGetSymbolAddress((void**)&q, g_q);
    cudaGetSymbolAddress((void**)&k, g_k);
    cudaGetSymbolAddress((void**)&vt, g_vt);
    cudaGetSymbolAddress((void**)&sc, g_scores);
    cudaGetSymbolAddress((void**)&ao, g_attnout);

    const int SMEM = (2 * A_STG + 2 * B_STG) * (int)sizeof(float);  // 110592
    cudaFuncSetAttribute((const void*)gemm_nt<true>,
                         cudaFuncAttributeMaxDynamicSharedMemorySize, SMEM);
    cudaFuncSetAttribute((const void*)gemm_nt<false>,
                         cudaFuncAttributeMaxDynamicSharedMemorySize, SMEM);

    const dim3 blk(256);

    // --- pre-round all GEMM inputs to tf32 ---
    {
        struct { const float* i; float* o; long n; } rr[7] = {
            {X,    xr,    (long)S_LEN * DMODEL},
            {Wqa,  wqar,  (long)QLORA * DMODEL},
            {Wkva, wkvar, (long)KVLORA * DMODEL},
            {Wqb,  wqbr,  (long)EQ * QLORA},
            {Wkb,  wkbr,  (long)EQ * KVLORA},
            {Wvb,  wvbr,  (long)EV * KVLORA},
            {Wo,   wor,   (long)DMODEL * EV},
        };
        for (int j = 0; j < 7; ++j) {
            int n4 = (int)(rr[j].n / 4);
            round_tf32_kernel<<<(n4 + 255) / 256, 256>>>(rr[j].i, rr[j].o, n4);
        }
    }

    // qlat = Xr @ Wqa^T  [1024,1536], split-K 4 x 1792
    gemm_nt<false><<<dim3(QLORA / 128, S_LEN / 256, 4), blk, SMEM>>>(
        xr, wqar, qlp, DMODEL, DMODEL, DMODEL, QLORA, 0, 0, (long)S_LEN * QLORA, 1792);
    {
        int n4 = S_LEN * QLORA / 4;
        reduce_k<4><<<(n4 + 255) / 256, 256>>>(qlp, qlat, n4, (long)n4);
    }
    // kvlat = Xr @ Wkva^T  [1024,512], split-K 8 x 896
    gemm_nt<false><<<dim3(KVLORA / 128, S_LEN / 256, 8), blk, SMEM>>>(
        xr, wkvar, kvlp, DMODEL, DMODEL, DMODEL, KVLORA, 0, 0, (long)S_LEN * KVLORA, 896);
    {
        int n4 = S_LEN * KVLORA / 4;
        reduce_k<8><<<(n4 + 255) / 256, 256>>>(kvlp, kvlat, n4, (long)n4);
    }

    // q = qlat @ Wqb^T   [1024, 24576]
    gemm_nt<true><<<dim3(EQ / 128, S_LEN / 256, 1), blk, SMEM>>>(
        qlat, wqbr, q, QLORA, QLORA, QLORA, EQ, 0, 0, 0, 0);
    // k = kvlat @ Wkb^T  [1024, 24576]
    gemm_nt<true><<<dim3(EQ / 128, S_LEN / 256, 1), blk, SMEM>>>(
        kvlat, wkbr, k, KVLORA, KVLORA, KVLORA, EQ, 0, 0, 0, 0);
    // vt = Wvbr @ kvlat^T  [16384, 1024]
    gemm_nt<true><<<dim3(S_LEN / 128, EV / 256, 1), blk, SMEM>>>(
        wvbr, kvlat, vt, KVLORA, KVLORA, KVLORA, S_LEN, 0, 0, 0, 0);

    rope_kernel<<<(S_LEN * NHEADS * 32) / 256, 256>>>(q);
    rope_kernel<<<(S_LEN * NHEADS * 32) / 256, 256>>>(k);

    // scores[h] = q_h @ k_h^T  (batched over heads, K=192)
    gemm_nt<false><<<dim3(S_LEN / 128, S_LEN / 256, NHEADS), blk, SMEM>>>(
        q, k, sc, DQd, EQ, EQ, S_LEN,
        (long)DQd, (long)DQd, (long)S_LEN * S_LEN, 0);

    softmax_kernel<<<NHEADS * S_LEN, 256>>>(sc);

    // attn_out[h] = P_h @ vt_h^T  (batched NT)
    gemm_nt<true><<<dim3(DVd / 128, S_LEN / 256, NHEADS), blk, SMEM>>>(
        sc, vt, ao, S_LEN, S_LEN, S_LEN, EV,
        (long)S_LEN * S_LEN, (long)DVd * S_LEN, (long)DVd, 0);

    // out = attn_out @ Wo^T  [1024, 7168]
    gemm_nt<false><<<dim3(DMODEL / 128, S_LEN / 256, 1), blk, SMEM>>>(
        ao, wor, out, EV, EV, EV, DMODEL, 0, 0, 0, 0);
}

// round 7
// speedup vs baseline: 1.0842x; 1.0842x over previous
#include <cuda_runtime.h>
#include <math.h>
#include <stdint.h>

#define S_LEN 1024
#define NHEADS 128
#define DQd 192
#define DNd 128
#define DVd 128
#define DMODEL 7168
#define QLORA 1536
#define KVLORA 512
#define EQ (NHEADS * DQd)   // 24576
#define EV (NHEADS * DVd)   // 16384

// ---- scratch (__device__ globals; allocation-free rule) ----
__device__ float g_xr[(size_t)S_LEN * DMODEL];
__device__ float g_wqar[(size_t)QLORA * DMODEL];
__device__ float g_wkvar[(size_t)KVLORA * DMODEL];
__device__ float g_wqbr[(size_t)EQ * QLORA];
__device__ float g_wkbr[(size_t)EQ * KVLORA];
__device__ float g_wvbr[(size_t)EV * KVLORA];
__device__ float g_wor[(size_t)DMODEL * EV];
__device__ float g_qlp[(size_t)4 * S_LEN * QLORA];
__device__ float g_kvlp[(size_t)8 * S_LEN * KVLORA];
__device__ float g_qlat[(size_t)S_LEN * QLORA];
__device__ float g_kvlat[(size_t)S_LEN * KVLORA];
__device__ float g_q[(size_t)S_LEN * EQ];
__device__ float g_k[(size_t)S_LEN * EQ];
__device__ float g_vt[(size_t)EV * S_LEN];           // V^T per head: [h*128+d][s]
__device__ float g_scores[(size_t)NHEADS * S_LEN * S_LEN];
__device__ float g_attnout[(size_t)S_LEN * EV];

__device__ __forceinline__ unsigned f2tf32(float x) {
    unsigned u;
    asm("cvt.rna.tf32.f32 %0, %1;" : "=r"(u) : "f"(x));
    return u;
}
__device__ __forceinline__ float f2tf32f(float x) { return __uint_as_float(f2tf32(x)); }

__device__ __forceinline__ void mma_tf32(float* d, const unsigned* a, const unsigned* b) {
    asm volatile(
        "mma.sync.aligned.m16n8k8.row.col.f32.tf32.tf32.f32 "
        "{%0,%1,%2,%3}, {%4,%5,%6,%7}, {%8,%9}, {%0,%1,%2,%3};"
        : "+f"(d[0]), "+f"(d[1]), "+f"(d[2]), "+f"(d[3])
        : "r"(a[0]), "r"(a[1]), "r"(a[2]), "r"(a[3]), "r"(b[0]), "r"(b[1]));
}

__device__ __forceinline__ void cp_async16(uint32_t dst, const void* src) {
    asm volatile("cp.async.cg.shared.global [%0], [%1], 16;\n" :: "r"(dst), "l"(src));
}
#define CP_COMMIT() asm volatile("cp.async.commit_group;\n" ::: "memory")
#define CP_WAIT0()  asm volatile("cp.async.wait_group 0;\n" ::: "memory")

// ---------------------------------------------------------------------------
// C[M,N] = A[M,K] @ B^T (B is [N,K] row-major). tf32 mma.sync, fp32 accum.
// BOTH operands must be tf32-pre-rounded in gmem (pure cp.async staging).
// Block tile 128x128, kTile 32, 8 warps of 32x64. Double-buffered, 2 CTAs/SM.
// M,N % 128 == 0, K % 32 == 0.
// kChunk > 0: split-K (z picks k-window and C plane z*sC); else z = batch.
// Dynamic smem: 2 * (128+128) * 36 floats = 73728 B.
// ---------------------------------------------------------------------------
#define SROW 36
#define TBUF (128 * SROW)

template <bool ROUND>
__global__ __launch_bounds__(256, 2) void gemm_nt(
    const float* __restrict__ Ag, const float* __restrict__ Bg, float* __restrict__ Cg,
    int K, int lda, int ldb, int ldc, long sA, long sB, long sC, int kChunk)
{
    extern __shared__ float sm[];
    float* SA = sm;              // [2][128][36]
    float* SB = sm + 2 * TBUF;   // [2][128][36]

    const int z = blockIdx.z;
    const float *A, *B;
    float* C;
    int Keff;
    if (kChunk) {
        A = Ag + (long)z * kChunk; B = Bg + (long)z * kChunk;
        C = Cg + (long)z * sC; Keff = kChunk;
    } else {
        A = Ag + (long)z * sA; B = Bg + (long)z * sB;
        C = Cg + (long)z * sC; Keff = K;
    }

    const int m0 = blockIdx.y * 128;
    const int n0 = blockIdx.x * 128;
    const int t = threadIdx.x, wid = t >> 5, lane = t & 31;
    const int wm = wid >> 1, wn = wid & 1;
    const int g = lane >> 2, tg = lane & 3;

    // staging: row = t>>1 (0..127), float4 cols (t&1) + 2i, i = 0..3
    const int srow = t >> 1;
    const int c4 = t & 1;
    const float* Ap = A + (long)(m0 + srow) * lda + c4 * 4;
    const float* Bp = B + (long)(n0 + srow) * ldb + c4 * 4;
    const uint32_t sa0 = (uint32_t)__cvta_generic_to_shared(&SA[srow * SROW + c4 * 4]);
    const uint32_t sb0 = (uint32_t)__cvta_generic_to_shared(&SB[srow * SROW + c4 * 4]);

    float acc[2][8][4] = {};

    // prologue: tile 0
#pragma unroll
    for (int i = 0; i < 4; ++i) {
        cp_async16(sa0 + i * 32, Ap + 8 * i);
        cp_async16(sb0 + i * 32, Bp + 8 * i);
    }
    CP_COMMIT();

    const int niter = Keff >> 5;
    for (int it = 0; it < niter; ++it) {
        const int cur = it & 1;
        CP_WAIT0();
        __syncthreads();

        // issue tile it+1 into the other buffer (overlaps with compute below)
        if (it + 1 < niter) {
            const int k0 = (it + 1) << 5;
            const uint32_t off = (cur ^ 1) * (TBUF * 4);
#pragma unroll
            for (int i = 0; i < 4; ++i) {
                cp_async16(sa0 + off + i * 32, Ap + k0 + 8 * i);
                cp_async16(sb0 + off + i * 32, Bp + k0 + 8 * i);
            }
            CP_COMMIT();
        }

        const float* sa = SA + cur * TBUF;
        const float* sb = SB + cur * TBUF;
#pragma unroll
        for (int kc = 0; kc < 4; ++kc) {
            const int kb = kc * 8;
            unsigned af[2][4];
#pragma unroll
            for (int mt = 0; mt < 2; ++mt) {
                const int r = wm * 32 + mt * 16 + g;
                af[mt][0] = __float_as_uint(sa[r * SROW + kb + tg]);
                af[mt][1] = __float_as_uint(sa[(r + 8) * SROW + kb + tg]);
                af[mt][2] = __float_as_uint(sa[r * SROW + kb + tg + 4]);
                af[mt][3] = __float_as_uint(sa[(r + 8) * SROW + kb + tg + 4]);
            }
#pragma unroll
            for (int nt = 0; nt < 8; ++nt) {
                const int n = wn * 64 + nt * 8 + g;
                unsigned bf[2];
                bf[0] = __float_as_uint(sb[n * SROW + kb + tg]);
                bf[1] = __float_as_uint(sb[n * SROW + kb + tg + 4]);
                mma_tf32(acc[0][nt], af[0], bf);
                mma_tf32(acc[1][nt], af[1], bf);
            }
        }
    }

    // epilogue
#pragma unroll
    for (int mt = 0; mt < 2; ++mt) {
        const int rr = m0 + wm * 32 + mt * 16 + g;
#pragma unroll
        for (int nt = 0; nt < 8; ++nt) {
            const int cc = n0 + wn * 64 + nt * 8 + tg * 2;
            float2 v0 = make_float2(acc[mt][nt][0], acc[mt][nt][1]);
            float2 v1 = make_float2(acc[mt][nt][2], acc[mt][nt][3]);
            if (ROUND) {
                v0.x = f2tf32f(v0.x); v0.y = f2tf32f(v0.y);
                v1.x = f2tf32f(v1.x); v1.y = f2tf32f(v1.y);
            }
            *(float2*)(C + (long)rr * ldc + cc)       = v0;
            *(float2*)(C + (long)(rr + 8) * ldc + cc) = v1;
        }
    }
}

// Elementwise tf32 rounding
__global__ void round_tf32_kernel(const float* __restrict__ in, float* __restrict__ out, int n4)
{
    int i = blockIdx.x * blockDim.x + threadIdx.x;
    if (i >= n4) return;
    float4 v = ((const float4*)in)[i];
    v.x = f2tf32f(v.x); v.y = f2tf32f(v.y); v.z = f2tf32f(v.z); v.w = f2tf32f(v.w);
    ((float4*)out)[i] = v;
}

// Split-K reduce: out[i] = round(sum_p in[i + p*stride4])
template <int P>
__global__ void reduce_k(const float* __restrict__ in, float* __restrict__ out,
                         int n4, long stride4)
{
    int i = blockIdx.x * blockDim.x + threadIdx.x;
    if (i >= n4) return;
    float4 s = ((const float4*)in)[i];
#pragma unroll
    for (int p = 1; p < P; ++p) {
        float4 v = ((const float4*)in)[i + (long)p * stride4];
        s.x += v.x; s.y += v.y; s.z += v.z; s.w += v.w;
    }
    s.x = f2tf32f(s.x); s.y = f2tf32f(s.y); s.z = f2tf32f(s.z); s.w = f2tf32f(s.w);
    ((float4*)out)[i] = s;
}

// Interleaved RoPE over dims [128,192). X: [S][H][192]. Writes tf32-rounded.
__global__ void rope_kernel(float* __restrict__ X)
{
    long idx = (long)blockIdx.x * blockDim.x + threadIdx.x;
    if (idx >= (long)S_LEN * NHEADS * 32) return;
    int i = (int)(idx & 31);
    int h = (int)((idx >> 5) & (NHEADS - 1));
    int s = (int)(idx >> 12);

    int m = (2 * i) & 31;
    float invf = (float)pow(10000.0, -(double)m / 32.0);
    float ang = (float)s * invf;
    float sn, cs;
    sincosf(ang, &sn, &cs);

    float* p = X + ((long)s * NHEADS + h) * DQd + DNd + 2 * i;
    float x1 = p[0], x2 = p[1];
    p[0] = f2tf32f(x1 * cs - x2 * sn);
    p[1] = f2tf32f(x1 * sn + x2 * cs);
}

// Row softmax with 1/sqrt(192) pre-scale; writes tf32-rounded probs.
__global__ __launch_bounds__(256) void softmax_kernel(float* __restrict__ P)
{
    float* row = P + (long)blockIdx.x * S_LEN;
    const int t = threadIdx.x;
    const int lane = t & 31, wid = t >> 5;
    const float scale = 0.07216878364870323f;

    float4 v = *(float4*)(row + t * 4);
    v.x *= scale; v.y *= scale; v.z *= scale; v.w *= scale;

    __shared__ float red[8];
    float lm = fmaxf(fmaxf(v.x, v.y), fmaxf(v.z, v.w));
#pragma unroll
    for (int o = 16; o; o >>= 1) lm = fmaxf(lm, __shfl_xor_sync(0xffffffffu, lm, o));
    if (lane == 0) red[wid] = lm;
    __syncthreads();
    float mall = red[0];
#pragma unroll
    for (int i = 1; i < 8; ++i) mall = fmaxf(mall, red[i]);

    float e0 = __expf(v.x - mall);
    float e1 = __expf(v.y - mall);
    float e2 = __expf(v.z - mall);
    float e3 = __expf(v.w - mall);
    float ls = e0 + e1 + e2 + e3;
#pragma unroll
    for (int o = 16; o; o >>= 1) ls += __shfl_xor_sync(0xffffffffu, ls, o);
    __syncthreads();
    if (lane == 0) red[wid] = ls;
    __syncthreads();
    float sall = 0.f;
#pragma unroll
    for (int i = 0; i < 8; ++i) sall += red[i];
    float inv = 1.f / sall;

    float4 o4 = make_float4(f2tf32f(e0 * inv), f2tf32f(e1 * inv),
                            f2tf32f(e2 * inv), f2tf32f(e3 * inv));
    *(float4*)(row + t * 4) = o4;
}

extern "C" void kernel_launch(void* const* d_in, const int* in_sizes, int n_in,
                              void* d_out, int out_size)
{
    const float* X    = (const float*)d_in[0];
    const float* Wqa  = (const float*)d_in[1];
    const float* Wkva = (const float*)d_in[2];
    const float* Wqb  = (const float*)d_in[3];
    const float* Wkb  = (const float*)d_in[4];
    const float* Wvb  = (const float*)d_in[5];
    const float* Wo   = (const float*)d_in[6];
    float* out = (float*)d_out;

    float *xr, *wqar, *wkvar, *wqbr, *wkbr, *wvbr, *wor;
    float *qlp, *kvlp, *qlat, *kvlat, *q, *k, *vt, *sc, *ao;
    cudaGetSymbolAddress((void**)&xr, g_xr);
    cudaGetSymbolAddress((void**)&wqar, g_wqar);
    cudaGetSymbolAddress((void**)&wkvar, g_wkvar);
    cudaGetSymbolAddress((void**)&wqbr, g_wqbr);
    cudaGetSymbolAddress((void**)&wkbr, g_wkbr);
    cudaGetSymbolAddress((void**)&wvbr, g_wvbr);
    cudaGetSymbolAddress((void**)&wor, g_wor);
    cudaGetSymbolAddress((void**)&qlp, g_qlp);
    cudaGetSymbolAddress((void**)&kvlp, g_kvlp);
    cudaGetSymbolAddress((void**)&qlat, g_qlat);
    cudaGetSymbolAddress((void**)&kvlat, g_kvlat);
    cudaGetSymbolAddress((void**)&q, g_q);
    cudaGetSymbolAddress((void**)&k, g_k);
    cudaGetSymbolAddress((void**)&vt, g_vt);
    cudaGetSymbolAddress((void**)&sc, g_scores);
    cudaGetSymbolAddress((void**)&ao, g_attnout);

    const int SMEM = 4 * TBUF * (int)sizeof(float);  // 73728
    cudaFuncSetAttribute((const void*)gemm_nt<true>,
                         cudaFuncAttributeMaxDynamicSharedMemorySize, SMEM);
    cudaFuncSetAttribute((const void*)gemm_nt<false>,
                         cudaFuncAttributeMaxDynamicSharedMemorySize, SMEM);

    const dim3 blk(256);

    // --- pre-round all GEMM inputs to tf32 ---
    {
        struct { const float* i; float* o; long n; } rr[7] = {
            {X,    xr,    (long)S_LEN * DMODEL},
            {Wqa,  wqar,  (long)QLORA * DMODEL},
            {Wkva, wkvar, (long)KVLORA * DMODEL},
            {Wqb,  wqbr,  (long)EQ * QLORA},
            {Wkb,  wkbr,  (long)EQ * KVLORA},
            {Wvb,  wvbr,  (long)EV * KVLORA},
            {Wo,   wor,   (long)DMODEL * EV},
        };
        for (int j = 0; j < 7; ++j) {
            int n4 = (int)(rr[j].n / 4);
            round_tf32_kernel<<<(n4 + 255) / 256, 256>>>(rr[j].i, rr[j].o, n4);
        }
    }

    // qlat = Xr @ Wqa^T  [1024,1536], split-K 4 x 1792
    gemm_nt<false><<<dim3(QLORA / 128, S_LEN / 128, 4), blk, SMEM>>>(
        xr, wqar, qlp, DMODEL, DMODEL, DMODEL, QLORA, 0, 0, (long)S_LEN * QLORA, 1792);
    {
        int n4 = S_LEN * QLORA / 4;
        reduce_k<4><<<(n4 + 255) / 256, 256>>>(qlp, qlat, n4, (long)n4);
    }
    // kvlat = Xr @ Wkva^T  [1024,512], split-K 8 x 896
    gemm_nt<false><<<dim3(KVLORA / 128, S_LEN / 128, 8), blk, SMEM>>>(
        xr, wkvar, kvlp, DMODEL, DMODEL, DMODEL, KVLORA, 0, 0, (long)S_LEN * KVLORA, 896);
    {
        int n4 = S_LEN * KVLORA / 4;
        reduce_k<8><<<(n4 + 255) / 256, 256>>>(kvlp, kvlat, n4, (long)n4);
    }

    // q = qlat @ Wqb^T   [1024, 24576]
    gemm_nt<true><<<dim3(EQ / 128, S_LEN / 128, 1), blk, SMEM>>>(
        qlat, wqbr, q, QLORA, QLORA, QLORA, EQ, 0, 0, 0, 0);
    // k = kvlat @ Wkb^T  [1024, 24576]
    gemm_nt<true><<<dim3(EQ / 128, S_LEN / 128, 1), blk, SMEM>>>(
        kvlat, wkbr, k, KVLORA, KVLORA, KVLORA, EQ, 0, 0, 0, 0);
    // vt = Wvbr @ kvlat^T  [16384, 1024]
    gemm_nt<true><<<dim3(S_LEN / 128, EV / 128, 1), blk, SMEM>>>(
        wvbr, kvlat, vt, KVLORA, KVLORA, KVLORA, S_LEN, 0, 0, 0, 0);

    rope_kernel<<<(S_LEN * NHEADS * 32) / 256, 256>>>(q);
    rope_kernel<<<(S_LEN * NHEADS * 32) / 256, 256>>>(k);

    // scores[h] = q_h @ k_h^T  (batched, K=192)
    gemm_nt<false><<<dim3(S_LEN / 128, S_LEN / 128, NHEADS), blk, SMEM>>>(
        q, k, sc, DQd, EQ, EQ, S_LEN,
        (long)DQd, (long)DQd, (long)S_LEN * S_LEN, 0);

    softmax_kernel<<<NHEADS * S_LEN, 256>>>(sc);

    // attn_out[h] = P_h @ vt_h^T  (batched NT)
    gemm_nt<true><<<dim3(DVd / 128, S_LEN / 128, NHEADS), blk, SMEM>>>(
        sc, vt, ao, S_LEN, S_LEN, S_LEN, EV,
        (long)S_LEN * S_LEN, (long)DVd * S_LEN, (long)DVd, 0);

    // out = attn_out @ Wo^T  [1024, 7168]
    gemm_nt<false><<<dim3(DMODEL / 128, S_LEN / 128, 1), blk, SMEM>>>(
        ao, wor, out, EV, EV, EV, DMODEL, 0, 0, 0, 0);
}

// round 12
// speedup vs baseline: 1.6817x; 1.5511x over previous
#include <cuda_runtime.h>
#include <cuda_fp16.h>
#include <math.h>
#include <stdint.h>

#define S_LEN 1024
#define NHEADS 128
#define DQd 192
#define DNd 128
#define DVd 128
#define DMODEL 7168
#define QLORA 1536
#define KVLORA 512
#define EQ (NHEADS * DQd)   // 24576
#define EV (NHEADS * DVd)   // 16384

// ---- scratch (__device__ globals; allocation-free rule) ----
__device__ __half g_xh[(size_t)S_LEN * DMODEL];
__device__ __half g_wqah[(size_t)QLORA * DMODEL];
__device__ __half g_wkvah[(size_t)KVLORA * DMODEL];
__device__ __half g_wqbh[(size_t)EQ * QLORA];
__device__ __half g_wkbh[(size_t)EQ * KVLORA];
__device__ __half g_wvbh[(size_t)EV * KVLORA];
__device__ __half g_woh[(size_t)DMODEL * EV];
__device__ float  g_qlp[(size_t)4 * S_LEN * QLORA];
__device__ float  g_kvlp[(size_t)8 * S_LEN * KVLORA];
__device__ __half g_qlath[(size_t)S_LEN * QLORA];
__device__ __half g_kvlath[(size_t)S_LEN * KVLORA];
__device__ __half g_qh[(size_t)S_LEN * EQ];
__device__ __half g_kh[(size_t)S_LEN * EQ];
__device__ __half g_vth[(size_t)EV * S_LEN];        // V^T per head: [h*128+d][s]
__device__ float  g_scores[(size_t)NHEADS * S_LEN * S_LEN];  // fp32 logits
__device__ __half g_probsh[(size_t)NHEADS * S_LEN * S_LEN];
__device__ __half g_aoh[(size_t)S_LEN * EV];

__device__ __forceinline__ void cp_async16(uint32_t dst, const void* src) {
    asm volatile("cp.async.cg.shared.global [%0], [%1], 16;\n" :: "r"(dst), "l"(src));
}
#define CP_COMMIT() asm volatile("cp.async.commit_group;\n" ::: "memory")
#define CP_WAIT0()  asm volatile("cp.async.wait_group 0;\n" ::: "memory")
#define CP_WAIT1()  asm volatile("cp.async.wait_group 1;\n" ::: "memory")

__device__ __forceinline__ void ldsm_x4(unsigned* r, uint32_t addr) {
    asm volatile("ldmatrix.sync.aligned.m8n8.x4.shared.b16 {%0,%1,%2,%3}, [%4];"
                 : "=r"(r[0]), "=r"(r[1]), "=r"(r[2]), "=r"(r[3]) : "r"(addr));
}
__device__ __forceinline__ void mma_f16(float* d, const unsigned* a, unsigned b0, unsigned b1) {
    asm volatile(
        "mma.sync.aligned.m16n8k16.row.col.f32.f16.f16.f32 "
        "{%0,%1,%2,%3}, {%4,%5,%6,%7}, {%8,%9}, {%0,%1,%2,%3};"
        : "+f"(d[0]), "+f"(d[1]), "+f"(d[2]), "+f"(d[3])
        : "r"(a[0]), "r"(a[1]), "r"(a[2]), "r"(a[3]), "r"(b0), "r"(b1));
}

// ---------------------------------------------------------------------------
// C[M,N] = A[M,K] @ B^T (B is [N,K] row-major), fp16 in, fp32 accumulate.
// Block 128x128, kTile 64 halves, 8 warps of 32x64 (m16n8k16 + ldmatrix).
// 3-stage cp.async pipeline (32KB/stage, 96KB total), 2 CTAs/SM.
// M,N % 128 == 0, K % 64 == 0. XOR swizzle: phys16Bchunk = logical ^ (row&7).
// OUT: 0 = fp32 C, 1 = fp16 C.
// kChunk>0: split-K (z = k-window, C plane z*sC); else z = batch via sA/sB/sC.
// ---------------------------------------------------------------------------
#define KT 64
#define STG_B 32768   // bytes per stage (A 16KB + B 16KB)

template <int OUT>
__global__ __launch_bounds__(256, 2) void hgemm_nt(
    const __half* __restrict__ Ag, const __half* __restrict__ Bg, void* __restrict__ Cg,
    int K, int lda, int ldb, int ldc, long sA, long sB, long sC, int kChunk)
{
    extern __shared__ char smraw[];
    const uint32_t smb = (uint32_t)__cvta_generic_to_shared(smraw);

    const int z = blockIdx.z;
    const __half *A, *B;
    int Keff;
    if (kChunk) { A = Ag + (long)z * kChunk; B = Bg + (long)z * kChunk; Keff = kChunk; }
    else        { A = Ag + (long)z * sA;     B = Bg + (long)z * sB;     Keff = K; }
    float*  Cf = (float*)Cg  + (long)z * sC;
    __half* Ch = (__half*)Cg + (long)z * sC;

    const int m0 = blockIdx.y * 128, n0 = blockIdx.x * 128;
    const int t = threadIdx.x, w = t >> 5, lane = t & 31;
    const int wm = w >> 1, wn = w & 1;

    // staging: row = t>>1, logical 16B chunks (t&1)*4 .. +3 (8 chunks/row = 64 halves)
    const int srow = t >> 1, c0 = (t & 1) * 4;
    const int rx = srow & 7;
    const __half* Asrc = A + (long)(m0 + srow) * lda + c0 * 8;
    const __half* Bsrc = B + (long)(n0 + srow) * ldb + c0 * 8;
    const uint32_t sAr = smb + srow * 128;
    const uint32_t sBr = smb + 16384 + srow * 128;

    float acc[2][8][4] = {};
    const int niter = Keff / KT;

    // prologue: stages 0,1
#pragma unroll
    for (int i = 0; i < 4; ++i) {
        cp_async16(sAr + (((c0 + i) ^ rx) << 4), Asrc + i * 8);
        cp_async16(sBr + (((c0 + i) ^ rx) << 4), Bsrc + i * 8);
    }
    CP_COMMIT();
    if (niter > 1) {
#pragma unroll
        for (int i = 0; i < 4; ++i) {
            cp_async16(sAr + STG_B + (((c0 + i) ^ rx) << 4), Asrc + KT + i * 8);
            cp_async16(sBr + STG_B + (((c0 + i) ^ rx) << 4), Bsrc + KT + i * 8);
        }
        CP_COMMIT();
    }

    // ldmatrix lane geometry
    const int a_r = (lane & 7) + ((lane >> 3) & 1) * 8;  // A: m within 16
    const int a_c = lane >> 4;                           // A: k-chunk half
    const int b_r = (lane & 7) + ((lane >> 4) & 1) * 8;  // B: n within 16
    const int b_c = (lane >> 3) & 1;                     // B: k-chunk half

    int stage = 0;
    for (int it = 0; it < niter; ++it) {
        if (it + 1 < niter) { CP_WAIT1(); } else { CP_WAIT0(); }
        __syncthreads();

        if (it + 2 < niter) {
            int ns = stage + 2; if (ns >= 3) ns -= 3;
            const uint32_t off = ns * STG_B;
            const int k0 = (it + 2) * KT;
#pragma unroll
            for (int i = 0; i < 4; ++i) {
                cp_async16(sAr + off + (((c0 + i) ^ rx) << 4), Asrc + k0 + i * 8);
                cp_async16(sBr + off + (((c0 + i) ^ rx) << 4), Bsrc + k0 + i * 8);
            }
            CP_COMMIT();
        }

        const uint32_t saA = smb + stage * STG_B;
        const uint32_t saB = saA + 16384;

#pragma unroll
        for (int kc = 0; kc < 4; ++kc) {       // 4 x k16
            unsigned af[2][4];
#pragma unroll
            for (int mt = 0; mt < 2; ++mt) {
                const int r = wm * 32 + mt * 16 + a_r;
                ldsm_x4(af[mt], saA + r * 128 + (((kc * 2 + a_c) ^ (r & 7)) << 4));
            }
#pragma unroll
            for (int ntt = 0; ntt < 4; ++ntt) {  // 2 n8-tiles per ldmatrix.x4
                const int r = wn * 64 + ntt * 16 + b_r;
                unsigned bf[4];
                ldsm_x4(bf, saB + r * 128 + (((kc * 2 + b_c) ^ (r & 7)) << 4));
#pragma unroll
                for (int mt = 0; mt < 2; ++mt) {
                    mma_f16(acc[mt][2 * ntt],     af[mt], bf[0], bf[1]);
                    mma_f16(acc[mt][2 * ntt + 1], af[mt], bf[2], bf[3]);
                }
            }
        }
        ++stage; if (stage == 3) stage = 0;
    }

    // epilogue
    const int g = lane >> 2, tq = lane & 3;
#pragma unroll
    for (int mt = 0; mt < 2; ++mt) {
        const int rr = m0 + wm * 32 + mt * 16 + g;
#pragma unroll
        for (int nt = 0; nt < 8; ++nt) {
            const int cc = n0 + wn * 64 + nt * 8 + tq * 2;
            if (OUT == 0) {
                *(float2*)(Cf + (long)rr * ldc + cc) =
                    make_float2(acc[mt][nt][0], acc[mt][nt][1]);
                *(float2*)(Cf + (long)(rr + 8) * ldc + cc) =
                    make_float2(acc[mt][nt][2], acc[mt][nt][3]);
            } else {
                *(__half2*)(Ch + (long)rr * ldc + cc) =
                    __floats2half2_rn(acc[mt][nt][0], acc[mt][nt][1]);
                *(__half2*)(Ch + (long)(rr + 8) * ldc + cc) =
                    __floats2half2_rn(acc[mt][nt][2], acc[mt][nt][3]);
            }
        }
    }
}

// ---- fused fp32 -> fp16 conversion of all 7 inputs (ONE launch) ----
// Segment walk gated on j == k: base advances only through segments
// strictly preceding the one containing this thread's index.
struct CvtPtrs { const float* s[7]; __half* d[7]; };
__global__ void cvt_all(CvtPtrs p)
{
    const long seg[7] = {1835008, 2752512, 917504, 9437184, 3145728, 2097152, 29360128};
    long i = (long)blockIdx.x * blockDim.x + threadIdx.x;
    long rem = i;
    int j = 0;
#pragma unroll
    for (int k = 0; k < 7; ++k) {
        if (j == k && rem >= seg[k]) { rem -= seg[k]; j = k + 1; }
    }
    if (j >= 7) return;
    float4 v = ((const float4*)p.s[j])[rem];
    __half2* dst = (__half2*)p.d[j] + rem * 2;
    dst[0] = __floats2half2_rn(v.x, v.y);
    dst[1] = __floats2half2_rn(v.z, v.w);
}

// Split-K reduce: fp32 partials -> fp16 output
template <int P>
__global__ void reduce_kh(const float* __restrict__ in, __half* __restrict__ out,
                          int n4, long stride4)
{
    int i = blockIdx.x * blockDim.x + threadIdx.x;
    if (i >= n4) return;
    float4 s = ((const float4*)in)[i];
#pragma unroll
    for (int p = 1; p < P; ++p) {
        float4 v = ((const float4*)in)[i + (long)p * stride4];
        s.x += v.x; s.y += v.y; s.z += v.z; s.w += v.w;
    }
    __half2* d = (__half2*)out + i * 2;
    d[0] = __floats2half2_rn(s.x, s.y);
    d[1] = __floats2half2_rn(s.z, s.w);
}

// Interleaved RoPE over dims [128,192) of each head vector. X: [S][H][192] fp16.
__global__ void rope_h(__half* __restrict__ X)
{
    long idx = (long)blockIdx.x * blockDim.x + threadIdx.x;
    if (idx >= (long)S_LEN * NHEADS * 32) return;
    int i = (int)(idx & 31);
    int h = (int)((idx >> 5) & (NHEADS - 1));
    int s = (int)(idx >> 12);

    int m = (2 * i) & 31;
    float invf = (float)pow(10000.0, -(double)m / 32.0);
    float ang = (float)s * invf;
    float sn, cs;
    sincosf(ang, &sn, &cs);

    __half2* p = (__half2*)(X + ((long)s * NHEADS + h) * DQd + DNd + 2 * i);
    float2 v = __half22float2(*p);
    *p = __floats2half2_rn(v.x * cs - v.y * sn, v.x * sn + v.y * cs);
}

// Row softmax over fp32 logits (scale fused), writes fp16 probs.
__global__ __launch_bounds__(256) void softmax_h(const float* __restrict__ S,
                                                 __half* __restrict__ Pb)
{
    const float* row = S + (long)blockIdx.x * S_LEN;
    __half* prow = Pb + (long)blockIdx.x * S_LEN;
    const int t = threadIdx.x;
    const int lane = t & 31, wid = t >> 5;
    const float scale = 0.07216878364870323f;  // 1/sqrt(192)

    float4 v = *(const float4*)(row + t * 4);
    v.x *= scale; v.y *= scale; v.z *= scale; v.w *= scale;

    __shared__ float red[8];
    float lm = fmaxf(fmaxf(v.x, v.y), fmaxf(v.z, v.w));
#pragma unroll
    for (int o = 16; o; o >>= 1) lm = fmaxf(lm, __shfl_xor_sync(0xffffffffu, lm, o));
    if (lane == 0) red[wid] = lm;
    __syncthreads();
    float mall = red[0];
#pragma unroll
    for (int i = 1; i < 8; ++i) mall = fmaxf(mall, red[i]);

    float e0 = __expf(v.x - mall);
    float e1 = __expf(v.y - mall);
    float e2 = __expf(v.z - mall);
    float e3 = __expf(v.w - mall);
    float ls = e0 + e1 + e2 + e3;
#pragma unroll
    for (int o = 16; o; o >>= 1) ls += __shfl_xor_sync(0xffffffffu, ls, o);
    __syncthreads();
    if (lane == 0) red[wid] = ls;
    __syncthreads();
    float sall = 0.f;
#pragma unroll
    for (int i = 0; i < 8; ++i) sall += red[i];
    float inv = 1.f / sall;

    __half2* d = (__half2*)(prow + t * 4);
    d[0] = __floats2half2_rn(e0 * inv, e1 * inv);
    d[1] = __floats2half2_rn(e2 * inv, e3 * inv);
}

extern "C" void kernel_launch(void* const* d_in, const int* in_sizes, int n_in,
                              void* d_out, int out_size)
{
    const float* X    = (const float*)d_in[0];
    const float* Wqa  = (const float*)d_in[1];
    const float* Wkva = (const float*)d_in[2];
    const float* Wqb  = (const float*)d_in[3];
    const float* Wkb  = (const float*)d_in[4];
    const float* Wvb  = (const float*)d_in[5];
    const float* Wo   = (const float*)d_in[6];
    float* out = (float*)d_out;

    __half *xh, *wqah, *wkvah, *wqbh, *wkbh, *wvbh, *woh;
    __half *qlath, *kvlath, *qh, *kh, *vth, *probsh, *aoh;
    float *qlp, *kvlp, *sc;
    cudaGetSymbolAddress((void**)&xh, g_xh);
    cudaGetSymbolAddress((void**)&wqah, g_wqah);
    cudaGetSymbolAddress((void**)&wkvah, g_wkvah);
    cudaGetSymbolAddress((void**)&wqbh, g_wqbh);
    cudaGetSymbolAddress((void**)&wkbh, g_wkbh);
    cudaGetSymbolAddress((void**)&wvbh, g_wvbh);
    cudaGetSymbolAddress((void**)&woh, g_woh);
    cudaGetSymbolAddress((void**)&qlp, g_qlp);
    cudaGetSymbolAddress((void**)&kvlp, g_kvlp);
    cudaGetSymbolAddress((void**)&qlath, g_qlath);
    cudaGetSymbolAddress((void**)&kvlath, g_kvlath);
    cudaGetSymbolAddress((void**)&qh, g_qh);
    cudaGetSymbolAddress((void**)&kh, g_kh);
    cudaGetSymbolAddress((void**)&vth, g_vth);
    cudaGetSymbolAddress((void**)&sc, g_scores);
    cudaGetSymbolAddress((void**)&probsh, g_probsh);
    cudaGetSymbolAddress((void**)&aoh, g_aoh);

    const int SMEM = 3 * STG_B;  // 98304
    cudaFuncSetAttribute((const void*)hgemm_nt<0>,
                         cudaFuncAttributeMaxDynamicSharedMemorySize, SMEM);
    cudaFuncSetAttribute((const void*)hgemm_nt<1>,
                         cudaFuncAttributeMaxDynamicSharedMemorySize, SMEM);

    const dim3 blk(256);

    // launch 0: fused fp32->fp16 conversion of all inputs
    {
        CvtPtrs p;
        p.s[0] = X;    p.d[0] = xh;
        p.s[1] = Wqa;  p.d[1] = wqah;
        p.s[2] = Wkva; p.d[2] = wkvah;
        p.s[3] = Wqb;  p.d[3] = wqbh;
        p.s[4] = Wkb;  p.d[4] = wkbh;
        p.s[5] = Wvb;  p.d[5] = wvbh;
        p.s[6] = Wo;   p.d[6] = woh;
        cvt_all<<<193536, 256>>>(p);
    }

    // launch 1: qlat partials = Xh @ Wqa^T  (split-K 4 x 1792)
    hgemm_nt<0><<<dim3(QLORA / 128, S_LEN / 128, 4), blk, SMEM>>>(
        xh, wqah, qlp, DMODEL, DMODEL, DMODEL, QLORA, 0, 0, (long)S_LEN * QLORA, 1792);
    // launch 2: kvlat partials (split-K 8 x 896)
    hgemm_nt<0><<<dim3(KVLORA / 128, S_LEN / 128, 8), blk, SMEM>>>(
        xh, wkvah, kvlp, DMODEL, DMODEL, DMODEL, KVLORA, 0, 0, (long)S_LEN * KVLORA, 896);
    // launch 3-4: reduces (fp32 -> fp16)
    {
        int n4 = S_LEN * QLORA / 4;
        reduce_kh<4><<<(n4 + 255) / 256, 256>>>(qlp, qlath, n4, (long)n4);
    }
    {
        int n4 = S_LEN * KVLORA / 4;
        reduce_kh<8><<<(n4 + 255) / 256, 256>>>(kvlp, kvlath, n4, (long)n4);
    }

    // launch 5 (ncu capture target): q = qlath @ Wqb^T  [1024, 24576]
    hgemm_nt<1><<<dim3(EQ / 128, S_LEN / 128, 1), blk, SMEM>>>(
        qlath, wqbh, qh, QLORA, QLORA, QLORA, EQ, 0, 0, 0, 0);
    // launch 6: k = kvlath @ Wkb^T
    hgemm_nt<1><<<dim3(EQ / 128, S_LEN / 128, 1), blk, SMEM>>>(
        kvlath, wkbh, kh, KVLORA, KVLORA, KVLORA, EQ, 0, 0, 0, 0);
    // launch 7: vt = Wvbh @ kvlath^T  [16384, 1024]
    hgemm_nt<1><<<dim3(S_LEN / 128, EV / 128, 1), blk, SMEM>>>(
        wvbh, kvlath, vth, KVLORA, KVLORA, KVLORA, S_LEN, 0, 0, 0, 0);

    // launches 8-9: RoPE
    rope_h<<<(S_LEN * NHEADS * 32) / 256, 256>>>(qh);
    rope_h<<<(S_LEN * NHEADS * 32) / 256, 256>>>(kh);

    // launch 10: scores[h] = q_h @ k_h^T  (fp32 logits, K=192)
    hgemm_nt<0><<<dim3(S_LEN / 128, S_LEN / 128, NHEADS), blk, SMEM>>>(
        qh, kh, sc, DQd, EQ, EQ, S_LEN,
        192, 192, (long)S_LEN * S_LEN, 0);

    // launch 11: softmax (fp32 -> fp16 probs)
    softmax_h<<<NHEADS * S_LEN, 256>>>(sc, probsh);

    // launch 12: attn_out[h] = P_h @ vt_h^T  (K=1024)
    hgemm_nt<1><<<dim3(DVd / 128, S_LEN / 128, NHEADS), blk, SMEM>>>(
        probsh, vth, aoh, S_LEN, S_LEN, S_LEN, EV,
        (long)S_LEN * S_LEN, (long)DVd * S_LEN, (long)DVd, 0);

    // launch 13: out = attn_out @ Wo^T  [1024, 7168] fp32
    hgemm_nt<0><<<dim3(DMODEL / 128, S_LEN / 128, 1), blk, SMEM>>>(
        aoh, woh, out, EV, EV, EV, DMODEL, 0, 0, 0, 0);
}

// round 13
// speedup vs baseline: 1.7472x; 1.0390x over previous
#include <cuda_runtime.h>
#include <cuda_fp16.h>
#include <math.h>
#include <stdint.h>

#define S_LEN 1024
#define NHEADS 128
#define DQd 192
#define DNd 128
#define DVd 128
#define DMODEL 7168
#define QLORA 1536
#define KVLORA 512
#define EQ (NHEADS * DQd)   // 24576
#define EV (NHEADS * DVd)   // 16384

// ---- scratch (__device__ globals; allocation-free rule) ----
__device__ __half g_xh[(size_t)S_LEN * DMODEL];
__device__ __half g_wqah[(size_t)QLORA * DMODEL];
__device__ __half g_wkvah[(size_t)KVLORA * DMODEL];
__device__ __half g_wqbh[(size_t)EQ * QLORA];
__device__ __half g_wkbh[(size_t)EQ * KVLORA];
__device__ __half g_wvbh[(size_t)EV * KVLORA];
__device__ __half g_woh[(size_t)DMODEL * EV];
__device__ float  g_qlp[(size_t)4 * S_LEN * QLORA];
__device__ float  g_kvlp[(size_t)8 * S_LEN * KVLORA];
__device__ __half g_qlath[(size_t)S_LEN * QLORA];
__device__ __half g_kvlath[(size_t)S_LEN * KVLORA];
__device__ __half g_qh[(size_t)S_LEN * EQ];
__device__ __half g_kh[(size_t)S_LEN * EQ];
__device__ __half g_vth[(size_t)EV * S_LEN];        // V^T per head: [h*128+d][s]
__device__ __half g_aoh[(size_t)S_LEN * EV];

__device__ __forceinline__ void cp_async16(uint32_t dst, const void* src) {
    asm volatile("cp.async.cg.shared.global [%0], [%1], 16;\n" :: "r"(dst), "l"(src));
}
#define CP_COMMIT() asm volatile("cp.async.commit_group;\n" ::: "memory")
#define CP_WAIT0()  asm volatile("cp.async.wait_group 0;\n" ::: "memory")
#define CP_WAIT1()  asm volatile("cp.async.wait_group 1;\n" ::: "memory")

__device__ __forceinline__ void ldsm_x4(unsigned* r, uint32_t addr) {
    asm volatile("ldmatrix.sync.aligned.m8n8.x4.shared.b16 {%0,%1,%2,%3}, [%4];"
                 : "=r"(r[0]), "=r"(r[1]), "=r"(r[2]), "=r"(r[3]) : "r"(addr));
}
__device__ __forceinline__ void mma_f16(float* d, const unsigned* a, unsigned b0, unsigned b1) {
    asm volatile(
        "mma.sync.aligned.m16n8k16.row.col.f32.f16.f16.f32 "
        "{%0,%1,%2,%3}, {%4,%5,%6,%7}, {%8,%9}, {%0,%1,%2,%3};"
        : "+f"(d[0]), "+f"(d[1]), "+f"(d[2]), "+f"(d[3])
        : "r"(a[0]), "r"(a[1]), "r"(a[2]), "r"(a[3]), "r"(b0), "r"(b1));
}
__device__ __forceinline__ unsigned ph2(float a, float b) {
    __half2 h = __floats2half2_rn(a, b);
    return *(unsigned*)&h;
}

// ---------------------------------------------------------------------------
// C[M,N] = A[M,K] @ B^T (B is [N,K] row-major), fp16 in, fp32 accumulate.
// Block 128x128, kTile 64 halves, 8 warps of 32x64 (m16n8k16 + ldmatrix).
// 3-stage cp.async pipeline (32KB/stage, 96KB total), 2 CTAs/SM.
// M,N % 128 == 0, K % 64 == 0. XOR swizzle: phys16Bchunk = logical ^ (row&7).
// OUT: 0 = fp32 C, 1 = fp16 C.
// kChunk>0: split-K (z = k-window, C plane z*sC); else z = batch via sA/sB/sC.
// ---------------------------------------------------------------------------
#define KT 64
#define STG_B 32768   // bytes per stage (A 16KB + B 16KB)

template <int OUT>
__global__ __launch_bounds__(256, 2) void hgemm_nt(
    const __half* __restrict__ Ag, const __half* __restrict__ Bg, void* __restrict__ Cg,
    int K, int lda, int ldb, int ldc, long sA, long sB, long sC, int kChunk)
{
    extern __shared__ char smraw[];
    const uint32_t smb = (uint32_t)__cvta_generic_to_shared(smraw);

    const int z = blockIdx.z;
    const __half *A, *B;
    int Keff;
    if (kChunk) { A = Ag + (long)z * kChunk; B = Bg + (long)z * kChunk; Keff = kChunk; }
    else        { A = Ag + (long)z * sA;     B = Bg + (long)z * sB;     Keff = K; }
    float*  Cf = (float*)Cg  + (long)z * sC;
    __half* Ch = (__half*)Cg + (long)z * sC;

    const int m0 = blockIdx.y * 128, n0 = blockIdx.x * 128;
    const int t = threadIdx.x, w = t >> 5, lane = t & 31;
    const int wm = w >> 1, wn = w & 1;

    const int srow = t >> 1, c0 = (t & 1) * 4;
    const int rx = srow & 7;
    const __half* Asrc = A + (long)(m0 + srow) * lda + c0 * 8;
    const __half* Bsrc = B + (long)(n0 + srow) * ldb + c0 * 8;
    const uint32_t sAr = smb + srow * 128;
    const uint32_t sBr = smb + 16384 + srow * 128;

    float acc[2][8][4] = {};
    const int niter = Keff / KT;

#pragma unroll
    for (int i = 0; i < 4; ++i) {
        cp_async16(sAr + (((c0 + i) ^ rx) << 4), Asrc + i * 8);
        cp_async16(sBr + (((c0 + i) ^ rx) << 4), Bsrc + i * 8);
    }
    CP_COMMIT();
    if (niter > 1) {
#pragma unroll
        for (int i = 0; i < 4; ++i) {
            cp_async16(sAr + STG_B + (((c0 + i) ^ rx) << 4), Asrc + KT + i * 8);
            cp_async16(sBr + STG_B + (((c0 + i) ^ rx) << 4), Bsrc + KT + i * 8);
        }
        CP_COMMIT();
    }

    const int a_r = (lane & 7) + ((lane >> 3) & 1) * 8;
    const int a_c = lane >> 4;
    const int b_r = (lane & 7) + ((lane >> 4) & 1) * 8;
    const int b_c = (lane >> 3) & 1;

    int stage = 0;
    for (int it = 0; it < niter; ++it) {
        if (it + 1 < niter) { CP_WAIT1(); } else { CP_WAIT0(); }
        __syncthreads();

        if (it + 2 < niter) {
            int ns = stage + 2; if (ns >= 3) ns -= 3;
            const uint32_t off = ns * STG_B;
            const int k0 = (it + 2) * KT;
#pragma unroll
            for (int i = 0; i < 4; ++i) {
                cp_async16(sAr + off + (((c0 + i) ^ rx) << 4), Asrc + k0 + i * 8);
                cp_async16(sBr + off + (((c0 + i) ^ rx) << 4), Bsrc + k0 + i * 8);
            }
            CP_COMMIT();
        }

        const uint32_t saA = smb + stage * STG_B;
        const uint32_t saB = saA + 16384;

#pragma unroll
        for (int kc = 0; kc < 4; ++kc) {
            unsigned af[2][4];
#pragma unroll
            for (int mt = 0; mt < 2; ++mt) {
                const int r = wm * 32 + mt * 16 + a_r;
                ldsm_x4(af[mt], saA + r * 128 + (((kc * 2 + a_c) ^ (r & 7)) << 4));
            }
#pragma unroll
            for (int ntt = 0; ntt < 4; ++ntt) {
                const int r = wn * 64 + ntt * 16 + b_r;
                unsigned bf[4];
                ldsm_x4(bf, saB + r * 128 + (((kc * 2 + b_c) ^ (r & 7)) << 4));
#pragma unroll
                for (int mt = 0; mt < 2; ++mt) {
                    mma_f16(acc[mt][2 * ntt],     af[mt], bf[0], bf[1]);
                    mma_f16(acc[mt][2 * ntt + 1], af[mt], bf[2], bf[3]);
                }
            }
        }
        ++stage; if (stage == 3) stage = 0;
    }

    const int g = lane >> 2, tq = lane & 3;
#pragma unroll
    for (int mt = 0; mt < 2; ++mt) {
        const int rr = m0 + wm * 32 + mt * 16 + g;
#pragma unroll
        for (int nt = 0; nt < 8; ++nt) {
            const int cc = n0 + wn * 64 + nt * 8 + tq * 2;
            if (OUT == 0) {
                *(float2*)(Cf + (long)rr * ldc + cc) =
                    make_float2(acc[mt][nt][0], acc[mt][nt][1]);
                *(float2*)(Cf + (long)(rr + 8) * ldc + cc) =
                    make_float2(acc[mt][nt][2], acc[mt][nt][3]);
            } else {
                *(__half2*)(Ch + (long)rr * ldc + cc) =
                    __floats2half2_rn(acc[mt][nt][0], acc[mt][nt][1]);
                *(__half2*)(Ch + (long)(rr + 8) * ldc + cc) =
                    __floats2half2_rn(acc[mt][nt][2], acc[mt][nt][3]);
            }
        }
    }
}

// ---------------------------------------------------------------------------
// Fused flash attention. Grid (8 q-blocks, 128 heads), 256 threads (8 warps).
// Each warp owns 16 q-rows. Per K/V block of 128 tokens:
//   QK^T (K=192) -> online softmax (fp32 stats, exp2) -> P(fp16) @ V (K=128).
// Q: smem 48KB (resident). K: 2 x 48KB stages. V: 2 x 32KB stages. = 208KB.
// Q/K smem rows 384B (24 x 16B chunks), V rows 256B (16 chunks); swizzle
// chunk ^= (row & 7) — ldsm reads 8 rows x 16B -> distinct bank groups.
// ---------------------------------------------------------------------------
#define FA_KSTG 49152
#define FA_VSTG 32768
#define FA_SMEM (FA_KSTG * 3 + FA_VSTG * 2)   // 212992

__global__ __launch_bounds__(256, 1) void flash_attn(
    const __half* __restrict__ Qg,   // [S][H][192]
    const __half* __restrict__ Kg,   // [S][H][192]
    const __half* __restrict__ Vt,   // [H*128][S]
    __half* __restrict__ Og)         // [S][H*128]
{
    extern __shared__ char smraw[];
    const uint32_t smb = (uint32_t)__cvta_generic_to_shared(smraw);
    const uint32_t Qs  = smb;
    const uint32_t Ks0 = smb + FA_KSTG;
    const uint32_t Vs0 = smb + FA_KSTG * 3;

    const int qb = blockIdx.x * 128;
    const int h  = blockIdx.y;
    const int t = threadIdx.x, w = t >> 5, lane = t & 31;
    const int g = lane >> 2, tq = lane & 3;

    // staging: Q/K 12 chunks/thread, V 8 chunks/thread
    const int srow = t >> 1, rx = srow & 7;
    const int cbase = (t & 1) * 12;
    const int vcbase = (t & 1) * 8;
    const __half* Qsrc = Qg + ((long)(qb + srow) * NHEADS + h) * DQd;
    const __half* Ksrc = Kg + ((long)srow * NHEADS + h) * DQd;
    const __half* Vsrc = Vt + (long)(h * 128 + srow) * S_LEN;
    const long KBLK = (long)128 * NHEADS * DQd;   // token-block stride in Kg

    // prologue: group0 = Q + K/V block 0; group1 = K/V block 1
#pragma unroll
    for (int i = 0; i < 12; ++i) {
        const int c = cbase + i;
        cp_async16(Qs  + srow * 384 + ((c ^ rx) << 4), Qsrc + c * 8);
        cp_async16(Ks0 + srow * 384 + ((c ^ rx) << 4), Ksrc + c * 8);
    }
#pragma unroll
    for (int i = 0; i < 8; ++i) {
        const int c = vcbase + i;
        cp_async16(Vs0 + srow * 256 + ((c ^ rx) << 4), Vsrc + c * 8);
    }
    CP_COMMIT();
#pragma unroll
    for (int i = 0; i < 12; ++i) {
        const int c = cbase + i;
        cp_async16(Ks0 + FA_KSTG + srow * 384 + ((c ^ rx) << 4), Ksrc + KBLK + c * 8);
    }
#pragma unroll
    for (int i = 0; i < 8; ++i) {
        const int c = vcbase + i;
        cp_async16(Vs0 + FA_VSTG + srow * 256 + ((c ^ rx) << 4), Vsrc + 128 + c * 8);
    }
    CP_COMMIT();

    const int a_r = (lane & 7) + ((lane >> 3) & 1) * 8;
    const int a_c = lane >> 4;
    const int b_r = (lane & 7) + ((lane >> 4) & 1) * 8;
    const int b_c = (lane >> 3) & 1;

    float oacc[16][4] = {};
    float m0 = -1e30f, m1 = -1e30f, l0 = 0.f, l1 = 0.f;
    const float ksc = 0.07216878364870323f * 1.4426950408889634f;  // scale*log2(e)

    for (int kb = 0; kb < 8; ++kb) {
        if (kb < 7) { CP_WAIT1(); } else { CP_WAIT0(); }
        __syncthreads();
        const uint32_t Kst = Ks0 + (kb & 1) * FA_KSTG;
        const uint32_t Vst = Vs0 + (kb & 1) * FA_VSTG;

        // --- QK^T: warp rows [w*16, w*16+16), all 128 tokens ---
        float sacc[16][4] = {};
#pragma unroll
        for (int kc = 0; kc < 12; ++kc) {
            unsigned aq[4];
            {
                const int r = w * 16 + a_r;
                ldsm_x4(aq, Qs + r * 384 + (((kc * 2 + a_c) ^ (r & 7)) << 4));
            }
#pragma unroll
            for (int ntt = 0; ntt < 8; ++ntt) {
                const int r = ntt * 16 + b_r;
                unsigned bk[4];
                ldsm_x4(bk, Kst + r * 384 + (((kc * 2 + b_c) ^ (r & 7)) << 4));
                mma_f16(sacc[2 * ntt],     aq, bk[0], bk[1]);
                mma_f16(sacc[2 * ntt + 1], aq, bk[2], bk[3]);
            }
        }

        // --- online softmax (rows r0 = w*16+g, r1 = r0+8) ---
        float bm0 = -1e30f, bm1 = -1e30f;
#pragma unroll
        for (int nt = 0; nt < 16; ++nt) {
            bm0 = fmaxf(bm0, fmaxf(sacc[nt][0], sacc[nt][1]));
            bm1 = fmaxf(bm1, fmaxf(sacc[nt][2], sacc[nt][3]));
        }
        bm0 = fmaxf(bm0, __shfl_xor_sync(0xffffffffu, bm0, 1));
        bm0 = fmaxf(bm0, __shfl_xor_sync(0xffffffffu, bm0, 2));
        bm1 = fmaxf(bm1, __shfl_xor_sync(0xffffffffu, bm1, 1));
        bm1 = fmaxf(bm1, __shfl_xor_sync(0xffffffffu, bm1, 2));
        const float mn0 = fmaxf(m0, bm0), mn1 = fmaxf(m1, bm1);
        const float al0 = exp2f(ksc * (m0 - mn0));
        const float al1 = exp2f(ksc * (m1 - mn1));
        l0 *= al0; l1 *= al1;
#pragma unroll
        for (int nt = 0; nt < 16; ++nt) {
            oacc[nt][0] *= al0; oacc[nt][1] *= al0;
            oacc[nt][2] *= al1; oacc[nt][3] *= al1;
        }
        m0 = mn0; m1 = mn1;

        // probs + repack C-frags -> A-frags (fp16)
        unsigned pa[8][4];
        float s0 = 0.f, s1 = 0.f;
#pragma unroll
        for (int j = 0; j < 8; ++j) {
            const float p00 = exp2f(ksc * (sacc[2*j][0] - mn0));
            const float p01 = exp2f(ksc * (sacc[2*j][1] - mn0));
            const float p02 = exp2f(ksc * (sacc[2*j][2] - mn1));
            const float p03 = exp2f(ksc * (sacc[2*j][3] - mn1));
            const float p10 = exp2f(ksc * (sacc[2*j+1][0] - mn0));
            const float p11 = exp2f(ksc * (sacc[2*j+1][1] - mn0));
            const float p12 = exp2f(ksc * (sacc[2*j+1][2] - mn1));
            const float p13 = exp2f(ksc * (sacc[2*j+1][3] - mn1));
            s0 += p00 + p01 + p10 + p11;
            s1 += p02 + p03 + p12 + p13;
            pa[j][0] = ph2(p00, p01);
            pa[j][1] = ph2(p02, p03);
            pa[j][2] = ph2(p10, p11);
            pa[j][3] = ph2(p12, p13);
        }
        s0 += __shfl_xor_sync(0xffffffffu, s0, 1);
        s0 += __shfl_xor_sync(0xffffffffu, s0, 2);
        s1 += __shfl_xor_sync(0xffffffffu, s1, 1);
        s1 += __shfl_xor_sync(0xffffffffu, s1, 2);
        l0 += s0; l1 += s1;

        // --- P @ V: K = 128 tokens (8 k16-chunks), N = dv 128 ---
#pragma unroll
        for (int j = 0; j < 8; ++j) {
#pragma unroll
            for (int nt2 = 0; nt2 < 8; ++nt2) {
                const int r = nt2 * 16 + b_r;
                unsigned bv[4];
                ldsm_x4(bv, Vst + r * 256 + (((j * 2 + b_c) ^ (r & 7)) << 4));
                mma_f16(oacc[2 * nt2],     pa[j], bv[0], bv[1]);
                mma_f16(oacc[2 * nt2 + 1], pa[j], bv[2], bv[3]);
            }
        }

        __syncthreads();   // all warps done reading stage kb&1
        if (kb + 2 < 8) {
            const long koff = (long)(kb + 2) * 128;
            const uint32_t Kd = Ks0 + (kb & 1) * FA_KSTG;
            const uint32_t Vd = Vs0 + (kb & 1) * FA_VSTG;
#pragma unroll
            for (int i = 0; i < 12; ++i) {
                const int c = cbase + i;
                cp_async16(Kd + srow * 384 + ((c ^ rx) << 4),
                           Ksrc + koff * NHEADS * DQd + c * 8);
            }
#pragma unroll
            for (int i = 0; i < 8; ++i) {
                const int c = vcbase + i;
                cp_async16(Vd + srow * 256 + ((c ^ rx) << 4), Vsrc + koff + c * 8);
            }
            CP_COMMIT();
        }
    }

    // epilogue: O /= l, write fp16 to [S][EV]
    const float i0 = 1.f / l0, i1 = 1.f / l1;
    const int r0 = qb + w * 16 + g;
    __half* orow0 = Og + (long)r0 * EV + h * 128;
    __half* orow1 = orow0 + (long)8 * EV;
#pragma unroll
    for (int nt = 0; nt < 16; ++nt) {
        *(__half2*)(orow0 + nt * 8 + tq * 2) =
            __floats2half2_rn(oacc[nt][0] * i0, oacc[nt][1] * i0);
        *(__half2*)(orow1 + nt * 8 + tq * 2) =
            __floats2half2_rn(oacc[nt][2] * i1, oacc[nt][3] * i1);
    }
}

// ---- fused fp32 -> fp16 conversion of all 7 inputs (ONE launch) ----
struct CvtPtrs { const float* s[7]; __half* d[7]; };
__global__ void cvt_all(CvtPtrs p)
{
    const long seg[7] = {1835008, 2752512, 917504, 9437184, 3145728, 2097152, 29360128};
    long i = (long)blockIdx.x * blockDim.x + threadIdx.x;
    long rem = i;
    int j = 0;
#pragma unroll
    for (int k = 0; k < 7; ++k) {
        if (j == k && rem >= seg[k]) { rem -= seg[k]; j = k + 1; }
    }
    if (j >= 7) return;
    float4 v = ((const float4*)p.s[j])[rem];
    __half2* dst = (__half2*)p.d[j] + rem * 2;
    dst[0] = __floats2half2_rn(v.x, v.y);
    dst[1] = __floats2half2_rn(v.z, v.w);
}

// Split-K reduce: fp32 partials -> fp16 output
template <int P>
__global__ void reduce_kh(const float* __restrict__ in, __half* __restrict__ out,
                          int n4, long stride4)
{
    int i = blockIdx.x * blockDim.x + threadIdx.x;
    if (i >= n4) return;
    float4 s = ((const float4*)in)[i];
#pragma unroll
    for (int p = 1; p < P; ++p) {
        float4 v = ((const float4*)in)[i + (long)p * stride4];
        s.x += v.x; s.y += v.y; s.z += v.z; s.w += v.w;
    }
    __half2* d = (__half2*)out + i * 2;
    d[0] = __floats2half2_rn(s.x, s.y);
    d[1] = __floats2half2_rn(s.z, s.w);
}

// Fused interleaved RoPE over dims [128,192) for BOTH q and k.
// Per-tensor index space is 2^22 (S*H*32).
__global__ void rope_qk(__half* __restrict__ Q, __half* __restrict__ K)
{
    long idx = (long)blockIdx.x * blockDim.x + threadIdx.x;
    if (idx >= (long)2 * S_LEN * NHEADS * 32) return;
    __half* X = (idx >> 22) ? K : Q;
    long id = idx & 0x3FFFFF;
    int i = (int)(id & 31);
    int h = (int)((id >> 5) & (NHEADS - 1));
    int s = (int)(id >> 12);

    int m = (2 * i) & 31;
    float invf = (float)pow(10000.0, -(double)m / 32.0);
    float ang = (float)s * invf;
    float sn, cs;
    sincosf(ang, &sn, &cs);

    __half2* p = (__half2*)(X + ((long)s * NHEADS + h) * DQd + DNd + 2 * i);
    float2 v = __half22float2(*p);
    *p = __floats2half2_rn(v.x * cs - v.y * sn, v.x * sn + v.y * cs);
}

extern "C" void kernel_launch(void* const* d_in, const int* in_sizes, int n_in,
                              void* d_out, int out_size)
{
    const float* X    = (const float*)d_in[0];
    const float* Wqa  = (const float*)d_in[1];
    const float* Wkva = (const float*)d_in[2];
    const float* Wqb  = (const float*)d_in[3];
    const float* Wkb  = (const float*)d_in[4];
    const float* Wvb  = (const float*)d_in[5];
    const float* Wo   = (const float*)d_in[6];
    float* out = (float*)d_out;

    __half *xh, *wqah, *wkvah, *wqbh, *wkbh, *wvbh, *woh;
    __half *qlath, *kvlath, *qh, *kh, *vth, *aoh;
    float *qlp, *kvlp;
    cudaGetSymbolAddress((void**)&xh, g_xh);
    cudaGetSymbolAddress((void**)&wqah, g_wqah);
    cudaGetSymbolAddress((void**)&wkvah, g_wkvah);
    cudaGetSymbolAddress((void**)&wqbh, g_wqbh);
    cudaGetSymbolAddress((void**)&wkbh, g_wkbh);
    cudaGetSymbolAddress((void**)&wvbh, g_wvbh);
    cudaGetSymbolAddress((void**)&woh, g_woh);
    cudaGetSymbolAddress((void**)&qlp, g_qlp);
    cudaGetSymbolAddress((void**)&kvlp, g_kvlp);
    cudaGetSymbolAddress((void**)&qlath, g_qlath);
    cudaGetSymbolAddress((void**)&kvlath, g_kvlath);
    cudaGetSymbolAddress((void**)&qh, g_qh);
    cudaGetSymbolAddress((void**)&kh, g_kh);
    cudaGetSymbolAddress((void**)&vth, g_vth);
    cudaGetSymbolAddress((void**)&aoh, g_aoh);

    const int SMEM = 3 * STG_B;  // 98304
    cudaFuncSetAttribute((const void*)hgemm_nt<0>,
                         cudaFuncAttributeMaxDynamicSharedMemorySize, SMEM);
    cudaFuncSetAttribute((const void*)hgemm_nt<1>,
                         cudaFuncAttributeMaxDynamicSharedMemorySize, SMEM);
    cudaFuncSetAttribute((const void*)flash_attn,
                         cudaFuncAttributeMaxDynamicSharedMemorySize, FA_SMEM);

    const dim3 blk(256);

    // launch 0: fused fp32->fp16 conversion of all inputs
    {
        CvtPtrs p;
        p.s[0] = X;    p.d[0] = xh;
        p.s[1] = Wqa;  p.d[1] = wqah;
        p.s[2] = Wkva; p.d[2] = wkvah;
        p.s[3] = Wqb;  p.d[3] = wqbh;
        p.s[4] = Wkb;  p.d[4] = wkbh;
        p.s[5] = Wvb;  p.d[5] = wvbh;
        p.s[6] = Wo;   p.d[6] = woh;
        cvt_all<<<193536, 256>>>(p);
    }

    // launch 1: kvlat partials (split-K 8 x 896)
    hgemm_nt<0><<<dim3(KVLORA / 128, S_LEN / 128, 8), blk, SMEM>>>(
        xh, wkvah, kvlp, DMODEL, DMODEL, DMODEL, KVLORA, 0, 0, (long)S_LEN * KVLORA, 896);
    // launch 2: reduce kvlat
    {
        int n4 = S_LEN * KVLORA / 4;
        reduce_kh<8><<<(n4 + 255) / 256, 256>>>(kvlp, kvlath, n4, (long)n4);
    }
    // launch 3 (ncu capture target): k = kvlath @ Wkb^T  [1024, 24576]
    hgemm_nt<1><<<dim3(EQ / 128, S_LEN / 128, 1), blk, SMEM>>>(
        kvlath, wkbh, kh, KVLORA, KVLORA, KVLORA, EQ, 0, 0, 0, 0);
    // launch 4: vt = Wvbh @ kvlath^T  [16384, 1024]
    hgemm_nt<1><<<dim3(S_LEN / 128, EV / 128, 1), blk, SMEM>>>(
        wvbh, kvlath, vth, KVLORA, KVLORA, KVLORA, S_LEN, 0, 0, 0, 0);
    // launch 5: qlat partials (split-K 4 x 1792)
    hgemm_nt<0><<<dim3(QLORA / 128, S_LEN / 128, 4), blk, SMEM>>>(
        xh, wqah, qlp, DMODEL, DMODEL, DMODEL, QLORA, 0, 0, (long)S_LEN * QLORA, 1792);
    // launch 6: reduce qlat
    {
        int n4 = S_LEN * QLORA / 4;
        reduce_kh<4><<<(n4 + 255) / 256, 256>>>(qlp, qlath, n4, (long)n4);
    }
    // launch 7: q = qlath @ Wqb^T  [1024, 24576]
    hgemm_nt<1><<<dim3(EQ / 128, S_LEN / 128, 1), blk, SMEM>>>(
        qlath, wqbh, qh, QLORA, QLORA, QLORA, EQ, 0, 0, 0, 0);

    // launch 8: fused RoPE on q and k
    rope_qk<<<(2 * S_LEN * NHEADS * 32) / 256, 256>>>(qh, kh);

    // launch 9: fused flash attention -> aoh fp16
    flash_attn<<<dim3(S_LEN / 128, NHEADS), blk, FA_SMEM>>>(qh, kh, vth, aoh);

    // launch 10: out = attn_out @ Wo^T  [1024, 7168] fp32
    hgemm_nt<0><<<dim3(DMODEL / 128, S_LEN / 128, 1), blk, SMEM>>>(
        aoh, woh, out, EV, EV, EV, DMODEL, 0, 0, 0, 0);
}

// round 14
// speedup vs baseline: 1.7507x; 1.0020x over previous
#include <cuda_runtime.h>
#include <cuda_fp16.h>
#include <math.h>
#include <stdint.h>

#define S_LEN 1024
#define NHEADS 128
#define DQd 192
#define DNd 128
#define DVd 128
#define DMODEL 7168
#define QLORA 1536
#define KVLORA 512
#define EQ (NHEADS * DQd)   // 24576
#define EV (NHEADS * DVd)   // 16384

// ---- scratch (__device__ globals; allocation-free rule) ----
__device__ __half g_xh[(size_t)S_LEN * DMODEL];
__device__ __half g_wqah[(size_t)QLORA * DMODEL];
__device__ __half g_wkvah[(size_t)KVLORA * DMODEL];
__device__ __half g_wqbh[(size_t)EQ * QLORA];
__device__ __half g_wkbh[(size_t)EQ * KVLORA];
__device__ __half g_wvbh[(size_t)EV * KVLORA];
__device__ __half g_woh[(size_t)DMODEL * EV];
__device__ float  g_qlp[(size_t)4 * S_LEN * QLORA];
__device__ float  g_kvlp[(size_t)8 * S_LEN * KVLORA];
__device__ __half g_qlath[(size_t)S_LEN * QLORA];
__device__ __half g_kvlath[(size_t)S_LEN * KVLORA];
__device__ __half g_qh[(size_t)S_LEN * EQ];
__device__ __half g_kh[(size_t)S_LEN * EQ];
__device__ __half g_vth[(size_t)EV * S_LEN];        // V^T per head: [h*128+d][s]
__device__ __half g_aoh[(size_t)S_LEN * EV];

__device__ __forceinline__ void cp_async16(uint32_t dst, const void* src) {
    asm volatile("cp.async.cg.shared.global [%0], [%1], 16;\n" :: "r"(dst), "l"(src));
}
#define CP_COMMIT() asm volatile("cp.async.commit_group;\n" ::: "memory")
#define CP_WAIT0()  asm volatile("cp.async.wait_group 0;\n" ::: "memory")
#define CP_WAIT1()  asm volatile("cp.async.wait_group 1;\n" ::: "memory")

__device__ __forceinline__ void ldsm_x4(unsigned* r, uint32_t addr) {
    asm volatile("ldmatrix.sync.aligned.m8n8.x4.shared.b16 {%0,%1,%2,%3}, [%4];"
                 : "=r"(r[0]), "=r"(r[1]), "=r"(r[2]), "=r"(r[3]) : "r"(addr));
}
__device__ __forceinline__ void mma_f16(float* d, const unsigned* a, unsigned b0, unsigned b1) {
    asm volatile(
        "mma.sync.aligned.m16n8k16.row.col.f32.f16.f16.f32 "
        "{%0,%1,%2,%3}, {%4,%5,%6,%7}, {%8,%9}, {%0,%1,%2,%3};"
        : "+f"(d[0]), "+f"(d[1]), "+f"(d[2]), "+f"(d[3])
        : "r"(a[0]), "r"(a[1]), "r"(a[2]), "r"(a[3]), "r"(b0), "r"(b1));
}
__device__ __forceinline__ unsigned ph2(float a, float b) {
    __half2 h = __floats2half2_rn(a, b);
    return *(unsigned*)&h;
}

// ---------------------------------------------------------------------------
// C[M,N] = A[M,K] @ B^T (B is [N,K] row-major), fp16 in, fp32 accumulate.
// Block 128x128, kTile 64 halves, 8 warps of 32x64 (m16n8k16 + ldmatrix).
// 3-stage cp.async pipeline (32KB/stage, 96KB total), 2 CTAs/SM.
// Fragment software pipelining: A-frags double-buffered across kc, B-frags
// across ntt — every ldsm issued ~one mma-group before its consumers.
// M,N % 128 == 0, K % 64 == 0. XOR swizzle: phys16Bchunk = logical ^ (row&7).
// OUT: 0 = fp32 C, 1 = fp16 C.
// SWAP: m0 from blockIdx.x (fast axis) — adjacent CTAs share the B tile
//       (weight-L2-reuse order for giant-B GEMMs).
// kChunk>0: split-K (z = k-window, C plane z*sC); else z = batch via sA/sB/sC.
// ---------------------------------------------------------------------------
#define KT 64
#define STG_B 32768   // bytes per stage (A 16KB + B 16KB)

template <int OUT, bool SWAP>
__global__ __launch_bounds__(256, 2) void hgemm_nt(
    const __half* __restrict__ Ag, const __half* __restrict__ Bg, void* __restrict__ Cg,
    int K, int lda, int ldb, int ldc, long sA, long sB, long sC, int kChunk)
{
    extern __shared__ char smraw[];
    const uint32_t smb = (uint32_t)__cvta_generic_to_shared(smraw);

    const int z = blockIdx.z;
    const __half *A, *B;
    int Keff;
    if (kChunk) { A = Ag + (long)z * kChunk; B = Bg + (long)z * kChunk; Keff = kChunk; }
    else        { A = Ag + (long)z * sA;     B = Bg + (long)z * sB;     Keff = K; }
    float*  Cf = (float*)Cg  + (long)z * sC;
    __half* Ch = (__half*)Cg + (long)z * sC;

    const int m0 = (SWAP ? blockIdx.x : blockIdx.y) * 128;
    const int n0 = (SWAP ? blockIdx.y : blockIdx.x) * 128;
    const int t = threadIdx.x, w = t >> 5, lane = t & 31;
    const int wm = w >> 1, wn = w & 1;

    const int srow = t >> 1, c0 = (t & 1) * 4;
    const int rx = srow & 7;
    const __half* Asrc = A + (long)(m0 + srow) * lda + c0 * 8;
    const __half* Bsrc = B + (long)(n0 + srow) * ldb + c0 * 8;
    const uint32_t sAr = smb + srow * 128;
    const uint32_t sBr = smb + 16384 + srow * 128;

    float acc[2][8][4] = {};
    const int niter = Keff / KT;

#pragma unroll
    for (int i = 0; i < 4; ++i) {
        cp_async16(sAr + (((c0 + i) ^ rx) << 4), Asrc + i * 8);
        cp_async16(sBr + (((c0 + i) ^ rx) << 4), Bsrc + i * 8);
    }
    CP_COMMIT();
    if (niter > 1) {
#pragma unroll
        for (int i = 0; i < 4; ++i) {
            cp_async16(sAr + STG_B + (((c0 + i) ^ rx) << 4), Asrc + KT + i * 8);
            cp_async16(sBr + STG_B + (((c0 + i) ^ rx) << 4), Bsrc + KT + i * 8);
        }
        CP_COMMIT();
    }

    const int a_r = (lane & 7) + ((lane >> 3) & 1) * 8;
    const int a_c = lane >> 4;
    const int b_r = (lane & 7) + ((lane >> 4) & 1) * 8;
    const int b_c = (lane >> 3) & 1;

    int stage = 0;
    for (int it = 0; it < niter; ++it) {
        if (it + 1 < niter) { CP_WAIT1(); } else { CP_WAIT0(); }
        __syncthreads();

        if (it + 2 < niter) {
            int ns = stage + 2; if (ns >= 3) ns -= 3;
            const uint32_t off = ns * STG_B;
            const int k0 = (it + 2) * KT;
#pragma unroll
            for (int i = 0; i < 4; ++i) {
                cp_async16(sAr + off + (((c0 + i) ^ rx) << 4), Asrc + k0 + i * 8);
                cp_async16(sBr + off + (((c0 + i) ^ rx) << 4), Bsrc + k0 + i * 8);
            }
            CP_COMMIT();
        }

        const uint32_t saA = smb + stage * STG_B;
        const uint32_t saB = saA + 16384;

        // fragment-pipelined mainloop
        unsigned af[2][2][4];   // [kc&1][mt]
        unsigned bf[2][4];      // [ntt&1]
        // preload A frags for kc=0
#pragma unroll
        for (int mt = 0; mt < 2; ++mt) {
            const int r = wm * 32 + mt * 16 + a_r;
            ldsm_x4(af[0][mt], saA + r * 128 + ((a_c ^ (r & 7)) << 4));
        }
#pragma unroll
        for (int kc = 0; kc < 4; ++kc) {
            // preload B frag for ntt=0
            {
                const int r = wn * 64 + b_r;
                ldsm_x4(bf[0], saB + r * 128 + (((kc * 2 + b_c) ^ (r & 7)) << 4));
            }
            // prefetch A frags for kc+1 (overlaps the whole ntt loop)
            if (kc < 3) {
#pragma unroll
                for (int mt = 0; mt < 2; ++mt) {
                    const int r = wm * 32 + mt * 16 + a_r;
                    ldsm_x4(af[(kc + 1) & 1][mt],
                            saA + r * 128 + ((((kc + 1) * 2 + a_c) ^ (r & 7)) << 4));
                }
            }
#pragma unroll
            for (int ntt = 0; ntt < 4; ++ntt) {
                if (ntt < 3) {  // prefetch B frag for ntt+1 before consuming ntt
                    const int r = wn * 64 + (ntt + 1) * 16 + b_r;
                    ldsm_x4(bf[(ntt + 1) & 1],
                            saB + r * 128 + (((kc * 2 + b_c) ^ (r & 7)) << 4));
                }
                const unsigned* bc = bf[ntt & 1];
#pragma unroll
                for (int mt = 0; mt < 2; ++mt) {
                    mma_f16(acc[mt][2 * ntt],     af[kc & 1][mt], bc[0], bc[1]);
                    mma_f16(acc[mt][2 * ntt + 1], af[kc & 1][mt], bc[2], bc[3]);
                }
            }
        }
        ++stage; if (stage == 3) stage = 0;
    }

    const int g = lane >> 2, tq = lane & 3;
#pragma unroll
    for (int mt = 0; mt < 2; ++mt) {
        const int rr = m0 + wm * 32 + mt * 16 + g;
#pragma unroll
        for (int nt = 0; nt < 8; ++nt) {
            const int cc = n0 + wn * 64 + nt * 8 + tq * 2;
            if (OUT == 0) {
                *(float2*)(Cf + (long)rr * ldc + cc) =
                    make_float2(acc[mt][nt][0], acc[mt][nt][1]);
                *(float2*)(Cf + (long)(rr + 8) * ldc + cc) =
                    make_float2(acc[mt][nt][2], acc[mt][nt][3]);
            } else {
                *(__half2*)(Ch + (long)rr * ldc + cc) =
                    __floats2half2_rn(acc[mt][nt][0], acc[mt][nt][1]);
                *(__half2*)(Ch + (long)(rr + 8) * ldc + cc) =
                    __floats2half2_rn(acc[mt][nt][2], acc[mt][nt][3]);
            }
        }
    }
}

// ---------------------------------------------------------------------------
// Fused flash attention (unchanged from R13 passing version).
// Grid (8 q-blocks, 128 heads), 256 threads (8 warps), 1 CTA/SM.
// ---------------------------------------------------------------------------
#define FA_KSTG 49152
#define FA_VSTG 32768
#define FA_SMEM (FA_KSTG * 3 + FA_VSTG * 2)   // 212992

__global__ __launch_bounds__(256, 1) void flash_attn(
    const __half* __restrict__ Qg,   // [S][H][192]
    const __half* __restrict__ Kg,   // [S][H][192]
    const __half* __restrict__ Vt,   // [H*128][S]
    __half* __restrict__ Og)         // [S][H*128]
{
    extern __shared__ char smraw[];
    const uint32_t smb = (uint32_t)__cvta_generic_to_shared(smraw);
    const uint32_t Qs  = smb;
    const uint32_t Ks0 = smb + FA_KSTG;
    const uint32_t Vs0 = smb + FA_KSTG * 3;

    const int qb = blockIdx.x * 128;
    const int h  = blockIdx.y;
    const int t = threadIdx.x, w = t >> 5, lane = t & 31;
    const int g = lane >> 2, tq = lane & 3;

    const int srow = t >> 1, rx = srow & 7;
    const int cbase = (t & 1) * 12;
    const int vcbase = (t & 1) * 8;
    const __half* Qsrc = Qg + ((long)(qb + srow) * NHEADS + h) * DQd;
    const __half* Ksrc = Kg + ((long)srow * NHEADS + h) * DQd;
    const __half* Vsrc = Vt + (long)(h * 128 + srow) * S_LEN;
    const long KBLK = (long)128 * NHEADS * DQd;

#pragma unroll
    for (int i = 0; i < 12; ++i) {
        const int c = cbase + i;
        cp_async16(Qs  + srow * 384 + ((c ^ rx) << 4), Qsrc + c * 8);
        cp_async16(Ks0 + srow * 384 + ((c ^ rx) << 4), Ksrc + c * 8);
    }
#pragma unroll
    for (int i = 0; i < 8; ++i) {
        const int c = vcbase + i;
        cp_async16(Vs0 + srow * 256 + ((c ^ rx) << 4), Vsrc + c * 8);
    }
    CP_COMMIT();
#pragma unroll
    for (int i = 0; i < 12; ++i) {
        const int c = cbase + i;
        cp_async16(Ks0 + FA_KSTG + srow * 384 + ((c ^ rx) << 4), Ksrc + KBLK + c * 8);
    }
#pragma unroll
    for (int i = 0; i < 8; ++i) {
        const int c = vcbase + i;
        cp_async16(Vs0 + FA_VSTG + srow * 256 + ((c ^ rx) << 4), Vsrc + 128 + c * 8);
    }
    CP_COMMIT();

    const int a_r = (lane & 7) + ((lane >> 3) & 1) * 8;
    const int a_c = lane >> 4;
    const int b_r = (lane & 7) + ((lane >> 4) & 1) * 8;
    const int b_c = (lane >> 3) & 1;

    float oacc[16][4] = {};
    float m0 = -1e30f, m1 = -1e30f, l0 = 0.f, l1 = 0.f;
    const float ksc = 0.07216878364870323f * 1.4426950408889634f;

    for (int kb = 0; kb < 8; ++kb) {
        if (kb < 7) { CP_WAIT1(); } else { CP_WAIT0(); }
        __syncthreads();
        const uint32_t Kst = Ks0 + (kb & 1) * FA_KSTG;
        const uint32_t Vst = Vs0 + (kb & 1) * FA_VSTG;

        float sacc[16][4] = {};
#pragma unroll
        for (int kc = 0; kc < 12; ++kc) {
            unsigned aq[4];
            {
                const int r = w * 16 + a_r;
                ldsm_x4(aq, Qs + r * 384 + (((kc * 2 + a_c) ^ (r & 7)) << 4));
            }
#pragma unroll
            for (int ntt = 0; ntt < 8; ++ntt) {
                const int r = ntt * 16 + b_r;
                unsigned bk[4];
                ldsm_x4(bk, Kst + r * 384 + (((kc * 2 + b_c) ^ (r & 7)) << 4));
                mma_f16(sacc[2 * ntt],     aq, bk[0], bk[1]);
                mma_f16(sacc[2 * ntt + 1], aq, bk[2], bk[3]);
            }
        }

        float bm0 = -1e30f, bm1 = -1e30f;
#pragma unroll
        for (int nt = 0; nt < 16; ++nt) {
            bm0 = fmaxf(bm0, fmaxf(sacc[nt][0], sacc[nt][1]));
            bm1 = fmaxf(bm1, fmaxf(sacc[nt][2], sacc[nt][3]));
        }
        bm0 = fmaxf(bm0, __shfl_xor_sync(0xffffffffu, bm0, 1));
        bm0 = fmaxf(bm0, __shfl_xor_sync(0xffffffffu, bm0, 2));
        bm1 = fmaxf(bm1, __shfl_xor_sync(0xffffffffu, bm1, 1));
        bm1 = fmaxf(bm1, __shfl_xor_sync(0xffffffffu, bm1, 2));
        const float mn0 = fmaxf(m0, bm0), mn1 = fmaxf(m1, bm1);
        const float al0 = exp2f(ksc * (m0 - mn0));
        const float al1 = exp2f(ksc * (m1 - mn1));
        l0 *= al0; l1 *= al1;
#pragma unroll
        for (int nt = 0; nt < 16; ++nt) {
            oacc[nt][0] *= al0; oacc[nt][1] *= al0;
            oacc[nt][2] *= al1; oacc[nt][3] *= al1;
        }
        m0 = mn0; m1 = mn1;

        unsigned pa[8][4];
        float s0 = 0.f, s1 = 0.f;
#pragma unroll
        for (int j = 0; j < 8; ++j) {
            const float p00 = exp2f(ksc * (sacc[2*j][0] - mn0));
            const float p01 = exp2f(ksc * (sacc[2*j][1] - mn0));
            const float p02 = exp2f(ksc * (sacc[2*j][2] - mn1));
            const float p03 = exp2f(ksc * (sacc[2*j][3] - mn1));
            const float p10 = exp2f(ksc * (sacc[2*j+1][0] - mn0));
            const float p11 = exp2f(ksc * (sacc[2*j+1][1] - mn0));
            const float p12 = exp2f(ksc * (sacc[2*j+1][2] - mn1));
            const float p13 = exp2f(ksc * (sacc[2*j+1][3] - mn1));
            s0 += p00 + p01 + p10 + p11;
            s1 += p02 + p03 + p12 + p13;
            pa[j][0] = ph2(p00, p01);
            pa[j][1] = ph2(p02, p03);
            pa[j][2] = ph2(p10, p11);
            pa[j][3] = ph2(p12, p13);
        }
        s0 += __shfl_xor_sync(0xffffffffu, s0, 1);
        s0 += __shfl_xor_sync(0xffffffffu, s0, 2);
        s1 += __shfl_xor_sync(0xffffffffu, s1, 1);
        s1 += __shfl_xor_sync(0xffffffffu, s1, 2);
        l0 += s0; l1 += s1;

#pragma unroll
        for (int j = 0; j < 8; ++j) {
#pragma unroll
            for (int nt2 = 0; nt2 < 8; ++nt2) {
                const int r = nt2 * 16 + b_r;
                unsigned bv[4];
                ldsm_x4(bv, Vst + r * 256 + (((j * 2 + b_c) ^ (r & 7)) << 4));
                mma_f16(oacc[2 * nt2],     pa[j], bv[0], bv[1]);
                mma_f16(oacc[2 * nt2 + 1], pa[j], bv[2], bv[3]);
            }
        }

        __syncthreads();
        if (kb + 2 < 8) {
            const long koff = (long)(kb + 2) * 128;
            const uint32_t Kd = Ks0 + (kb & 1) * FA_KSTG;
            const uint32_t Vd = Vs0 + (kb & 1) * FA_VSTG;
#pragma unroll
            for (int i = 0; i < 12; ++i) {
                const int c = cbase + i;
                cp_async16(Kd + srow * 384 + ((c ^ rx) << 4),
                           Ksrc + koff * NHEADS * DQd + c * 8);
            }
#pragma unroll
            for (int i = 0; i < 8; ++i) {
                const int c = vcbase + i;
                cp_async16(Vd + srow * 256 + ((c ^ rx) << 4), Vsrc + koff + c * 8);
            }
            CP_COMMIT();
        }
    }

    const float i0 = 1.f / l0, i1 = 1.f / l1;
    const int r0 = qb + w * 16 + g;
    __half* orow0 = Og + (long)r0 * EV + h * 128;
    __half* orow1 = orow0 + (long)8 * EV;
#pragma unroll
    for (int nt = 0; nt < 16; ++nt) {
        *(__half2*)(orow0 + nt * 8 + tq * 2) =
            __floats2half2_rn(oacc[nt][0] * i0, oacc[nt][1] * i0);
        *(__half2*)(orow1 + nt * 8 + tq * 2) =
            __floats2half2_rn(oacc[nt][2] * i1, oacc[nt][3] * i1);
    }
}

// ---- fused fp32 -> fp16 conversion of all 7 inputs (ONE launch) ----
struct CvtPtrs { const float* s[7]; __half* d[7]; };
__global__ void cvt_all(CvtPtrs p)
{
    const long seg[7] = {1835008, 2752512, 917504, 9437184, 3145728, 2097152, 29360128};
    long i = (long)blockIdx.x * blockDim.x + threadIdx.x;
    long rem = i;
    int j = 0;
#pragma unroll
    for (int k = 0; k < 7; ++k) {
        if (j == k && rem >= seg[k]) { rem -= seg[k]; j = k + 1; }
    }
    if (j >= 7) return;
    float4 v = ((const float4*)p.s[j])[rem];
    __half2* dst = (__half2*)p.d[j] + rem * 2;
    dst[0] = __floats2half2_rn(v.x, v.y);
    dst[1] = __floats2half2_rn(v.z, v.w);
}

// Split-K reduce: fp32 partials -> fp16 output
template <int P>
__global__ void reduce_kh(const float* __restrict__ in, __half* __restrict__ out,
                          int n4, long stride4)
{
    int i = blockIdx.x * blockDim.x + threadIdx.x;
    if (i >= n4) return;
    float4 s = ((const float4*)in)[i];
#pragma unroll
    for (int p = 1; p < P; ++p) {
        float4 v = ((const float4*)in)[i + (long)p * stride4];
        s.x += v.x; s.y += v.y; s.z += v.z; s.w += v.w;
    }
    __half2* d = (__half2*)out + i * 2;
    d[0] = __floats2half2_rn(s.x, s.y);
    d[1] = __floats2half2_rn(s.z, s.w);
}

// Fused interleaved RoPE over dims [128,192) for BOTH q and k.
__global__ void rope_qk(__half* __restrict__ Q, __half* __restrict__ K)
{
    long idx = (long)blockIdx.x * blockDim.x + threadIdx.x;
    if (idx >= (long)2 * S_LEN * NHEADS * 32) return;
    __half* X = (idx >> 22) ? K : Q;
    long id = idx & 0x3FFFFF;
    int i = (int)(id & 31);
    int h = (int)((id >> 5) & (NHEADS - 1));
    int s = (int)(id >> 12);

    int m = (2 * i) & 31;
    float invf = (float)pow(10000.0, -(double)m / 32.0);
    float ang = (float)s * invf;
    float sn, cs;
    sincosf(ang, &sn, &cs);

    __half2* p = (__half2*)(X + ((long)s * NHEADS + h) * DQd + DNd + 2 * i);
    float2 v = __half22float2(*p);
    *p = __floats2half2_rn(v.x * cs - v.y * sn, v.x * sn + v.y * cs);
}

extern "C" void kernel_launch(void* const* d_in, const int* in_sizes, int n_in,
                              void* d_out, int out_size)
{
    const float* X    = (const float*)d_in[0];
    const float* Wqa  = (const float*)d_in[1];
    const float* Wkva = (const float*)d_in[2];
    const float* Wqb  = (const float*)d_in[3];
    const float* Wkb  = (const float*)d_in[4];
    const float* Wvb  = (const float*)d_in[5];
    const float* Wo   = (const float*)d_in[6];
    float* out = (float*)d_out;

    __half *xh, *wqah, *wkvah, *wqbh, *wkbh, *wvbh, *woh;
    __half *qlath, *kvlath, *qh, *kh, *vth, *aoh;
    float *qlp, *kvlp;
    cudaGetSymbolAddress((void**)&xh, g_xh);
    cudaGetSymbolAddress((void**)&wqah, g_wqah);
    cudaGetSymbolAddress((void**)&wkvah, g_wkvah);
    cudaGetSymbolAddress((void**)&wqbh, g_wqbh);
    cudaGetSymbolAddress((void**)&wkbh, g_wkbh);
    cudaGetSymbolAddress((void**)&wvbh, g_wvbh);
    cudaGetSymbolAddress((void**)&woh, g_woh);
    cudaGetSymbolAddress((void**)&qlp, g_qlp);
    cudaGetSymbolAddress((void**)&kvlp, g_kvlp);
    cudaGetSymbolAddress((void**)&qlath, g_qlath);
    cudaGetSymbolAddress((void**)&kvlath, g_kvlath);
    cudaGetSymbolAddress((void**)&qh, g_qh);
    cudaGetSymbolAddress((void**)&kh, g_kh);
    cudaGetSymbolAddress((void**)&vth, g_vth);
    cudaGetSymbolAddress((void**)&aoh, g_aoh);

    const int SMEM = 3 * STG_B;  // 98304
    cudaFuncSetAttribute((const void*)hgemm_nt<0, false>,
                         cudaFuncAttributeMaxDynamicSharedMemorySize, SMEM);
    cudaFuncSetAttribute((const void*)hgemm_nt<0, true>,
                         cudaFuncAttributeMaxDynamicSharedMemorySize, SMEM);
    cudaFuncSetAttribute((const void*)hgemm_nt<1, false>,
                         cudaFuncAttributeMaxDynamicSharedMemorySize, SMEM);
    cudaFuncSetAttribute((const void*)hgemm_nt<1, true>,
                         cudaFuncAttributeMaxDynamicSharedMemorySize, SMEM);
    cudaFuncSetAttribute((const void*)flash_attn,
                         cudaFuncAttributeMaxDynamicSharedMemorySize, FA_SMEM);

    const dim3 blk(256);

    // launch 0: fused fp32->fp16 conversion of all inputs
    {
        CvtPtrs p;
        p.s[0] = X;    p.d[0] = xh;
        p.s[1] = Wqa;  p.d[1] = wqah;
        p.s[2] = Wkva; p.d[2] = wkvah;
        p.s[3] = Wqb;  p.d[3] = wqbh;
        p.s[4] = Wkb;  p.d[4] = wkbh;
        p.s[5] = Wvb;  p.d[5] = wvbh;
        p.s[6] = Wo;   p.d[6] = woh;
        cvt_all<<<193536, 256>>>(p);
    }

    // launch 1: kvlat partials (split-K 8 x 896)
    hgemm_nt<0, false><<<dim3(KVLORA / 128, S_LEN / 128, 8), blk, SMEM>>>(
        xh, wkvah, kvlp, DMODEL, DMODEL, DMODEL, KVLORA, 0, 0, (long)S_LEN * KVLORA, 896);
    // launch 2: reduce kvlat
    {
        int n4 = S_LEN * KVLORA / 4;
        reduce_kh<8><<<(n4 + 255) / 256, 256>>>(kvlp, kvlath, n4, (long)n4);
    }
    // launch 3 (ncu capture target): k = kvlath @ Wkb^T  [1024, 24576]
    hgemm_nt<1, false><<<dim3(EQ / 128, S_LEN / 128, 1), blk, SMEM>>>(
        kvlath, wkbh, kh, KVLORA, KVLORA, KVLORA, EQ, 0, 0, 0, 0);
    // launch 4: vt = Wvbh @ kvlath^T  [16384, 1024]
    hgemm_nt<1, false><<<dim3(S_LEN / 128, EV / 128, 1), blk, SMEM>>>(
        wvbh, kvlath, vth, KVLORA, KVLORA, KVLORA, S_LEN, 0, 0, 0, 0);
    // launch 5: qlat partials (split-K 4 x 1792)
    hgemm_nt<0, false><<<dim3(QLORA / 128, S_LEN / 128, 4), blk, SMEM>>>(
        xh, wqah, qlp, DMODEL, DMODEL, DMODEL, QLORA, 0, 0, (long)S_LEN * QLORA, 1792);
    // launch 6: reduce qlat
    {
        int n4 = S_LEN * QLORA / 4;
        reduce_kh<4><<<(n4 + 255) / 256, 256>>>(qlp, qlath, n4, (long)n4);
    }
    // launch 7: q = qlath @ Wqb^T  [1024, 24576]  (SWAP: weight-reuse order)
    hgemm_nt<1, true><<<dim3(S_LEN / 128, EQ / 128, 1), blk, SMEM>>>(
        qlath, wqbh, qh, QLORA, QLORA, QLORA, EQ, 0, 0, 0, 0);

    // launch 8: fused RoPE on q and k
    rope_qk<<<(2 * S_LEN * NHEADS * 32) / 256, 256>>>(qh, kh);

    // launch 9: fused flash attention -> aoh fp16
    flash_attn<<<dim3(S_LEN / 128, NHEADS), blk, FA_SMEM>>>(qh, kh, vth, aoh);

    // launch 10: out = attn_out @ Wo^T  [1024, 7168] fp32  (SWAP)
    hgemm_nt<0, true><<<dim3(S_LEN / 128, DMODEL / 128, 1), blk, SMEM>>>(
        aoh, woh, out, EV, EV, EV, DMODEL, 0, 0, 0, 0);
}